// round 1
// baseline (speedup 1.0000x reference)
#include <cuda_runtime.h>

// ---------------------------------------------------------------------------
// GCN 3-layer + mean-pool + MLP for GB300 (sm_103a)
// Fixed problem shape: N=50000, E=800000, D=3, H=128, G=64, H2=64, C=10
// ---------------------------------------------------------------------------

#define HDIM 128
#define MAXN 50176
#define MAXG 256

// Index type: JAX with x64 disabled demotes int64 -> int32. Guarded reads below
// make a wrong guess fail correctness cleanly instead of crashing.
typedef int idx_t;

// Scratch (static device globals; no allocation allowed)
__device__ float g_h[MAXN * HDIM];     // dense-transform output
__device__ float g_y[MAXN * HDIM];     // aggregated output / next-layer input
__device__ float g_deg[MAXN];          // degree, then dinv (in place)
__device__ float g_gsum[MAXG * HDIM];  // per-graph sums
__device__ float g_gcnt[MAXG];         // per-graph counts

// ---------------------------------------------------------------------------
__global__ void init_kernel(int N, int GH, int G) {
    int i = blockIdx.x * blockDim.x + threadIdx.x;
    if (i < N) g_deg[i] = 1.0f;           // self-loop contributes 1
    if (i < GH) g_gsum[i] = 0.0f;
    if (i < G) g_gcnt[i] = 0.0f;
}

__global__ void deg_kernel(const idx_t* __restrict__ ei, int E, int N) {
    int e = blockIdx.x * blockDim.x + threadIdx.x;
    if (e >= E) return;
    int d = (int)ei[(long long)E + e];
    if ((unsigned)d < (unsigned)N) atomicAdd(&g_deg[d], 1.0f);
}

__global__ void dinv_kernel(int N) {
    int i = blockIdx.x * blockDim.x + threadIdx.x;
    if (i < N) g_deg[i] = rsqrtf(g_deg[i]);
}

// Layer-1 dense: h = pos @ W1   (D small, one block per node, thread per col)
__global__ void dense1_kernel(const float* __restrict__ pos,
                              const float* __restrict__ W1, int N, int D) {
    int n = blockIdx.x;
    int j = threadIdx.x;
    if (n >= N) return;
    float s = 0.0f;
    for (int d = 0; d < D; d++)
        s += pos[n * D + d] * W1[d * HDIM + j];
    g_h[n * HDIM + j] = s;
}

// Aggregation init: y = b + h * dinv^2  (bias + self-loop message)
__global__ void agg_init_kernel(const float* __restrict__ b, int N) {
    int u = blockIdx.x * blockDim.x + threadIdx.x;   // over N*32 float4 units
    if (u >= N * 32) return;
    int n = u >> 5, q = u & 31;
    float di = g_deg[n];
    float w = di * di;
    float4 h4 = *(const float4*)&g_h[n * HDIM + q * 4];
    float4 b4 = *(const float4*)&b[q * 4];
    float4 o;
    o.x = b4.x + h4.x * w;
    o.y = b4.y + h4.y * w;
    o.z = b4.z + h4.z * w;
    o.w = b4.w + h4.w * w;
    *(float4*)&g_y[n * HDIM + q * 4] = o;
}

// Edge aggregation: warp per edge, lane handles float4 (32*4 = 128 = H).
// y[dst] += h[src] * dinv[src]*dinv[dst]   via red.global.add.v4.f32
__global__ void agg_edge_kernel(const idx_t* __restrict__ ei, int E, int N) {
    int w = blockIdx.x * (blockDim.x >> 5) + (threadIdx.x >> 5);
    if (w >= E) return;
    int lane = threadIdx.x & 31;
    int s = (int)__ldg(&ei[w]);
    int d = (int)__ldg(&ei[(long long)E + w]);
    if ((unsigned)s >= (unsigned)N || (unsigned)d >= (unsigned)N) return;
    float nrm = g_deg[s] * g_deg[d];
    float4 v = *(const float4*)&g_h[s * HDIM + lane * 4];
    float* p = &g_y[d * HDIM + lane * 4];
    asm volatile("red.global.add.v4.f32 [%0], {%1,%2,%3,%4};"
                 :: "l"(p), "f"(v.x * nrm), "f"(v.y * nrm),
                    "f"(v.z * nrm), "f"(v.w * nrm)
                 : "memory");
}

// Dense layers 2/3: h = relu(y) @ W, register-blocked shared-memory GEMM.
// Block = 256 threads, 64 nodes x 128 cols per block; thread = 8 nodes x 4 cols.
__global__ void __launch_bounds__(256)
dense_relu_kernel(const float* __restrict__ W, int N) {
    __shared__ float Ws[32 * 128];      // k-chunk of W, [kk][col]
    __shared__ float Xs[32 * 65];       // transposed relu(y), [kk][node], pad 65
    int tid = threadIdx.x;
    int tc = tid & 31;                  // col group (4 cols)
    int tr = tid >> 5;                  // node group (8 nodes)
    int n0 = blockIdx.x * 64;

    float acc[8][4];
#pragma unroll
    for (int i = 0; i < 8; i++)
#pragma unroll
        for (int j = 0; j < 4; j++) acc[i][j] = 0.0f;

    for (int k0 = 0; k0 < HDIM; k0 += 32) {
        __syncthreads();
        // load W chunk: 32x128 floats = 1024 float4, 4 per thread
#pragma unroll
        for (int t = 0; t < 4; t++) {
            int i = tid + t * 256;
            int kk = i >> 5, cq = i & 31;
            *(float4*)&Ws[kk * 128 + cq * 4] =
                *(const float4*)&W[(k0 + kk) * HDIM + cq * 4];
        }
        // load X chunk (relu on read): 64 nodes x 8 float4, 2 per thread
#pragma unroll
        for (int t = 0; t < 2; t++) {
            int i = tid + t * 256;
            int nn = i >> 3, kq = i & 7;
            int node = n0 + nn;
            float4 v = make_float4(0.f, 0.f, 0.f, 0.f);
            if (node < N)
                v = *(const float4*)&g_y[node * HDIM + k0 + kq * 4];
            Xs[(kq * 4 + 0) * 65 + nn] = fmaxf(v.x, 0.f);
            Xs[(kq * 4 + 1) * 65 + nn] = fmaxf(v.y, 0.f);
            Xs[(kq * 4 + 2) * 65 + nn] = fmaxf(v.z, 0.f);
            Xs[(kq * 4 + 3) * 65 + nn] = fmaxf(v.w, 0.f);
        }
        __syncthreads();
#pragma unroll
        for (int kk = 0; kk < 32; kk++) {
            float4 w4 = *(float4*)&Ws[kk * 128 + tc * 4];
#pragma unroll
            for (int i = 0; i < 8; i++) {
                float x = Xs[kk * 65 + tr * 8 + i];
                acc[i][0] += x * w4.x;
                acc[i][1] += x * w4.y;
                acc[i][2] += x * w4.z;
                acc[i][3] += x * w4.w;
            }
        }
    }
#pragma unroll
    for (int i = 0; i < 8; i++) {
        int node = n0 + tr * 8 + i;
        if (node < N) {
            float4 o = make_float4(acc[i][0], acc[i][1], acc[i][2], acc[i][3]);
            *(float4*)&g_h[node * HDIM + tc * 4] = o;
        }
    }
}

// Mean-pool numerator/denominator: warp per node, relu on read
__global__ void pool_kernel(const idx_t* __restrict__ batch, int N, int G) {
    int n = blockIdx.x * (blockDim.x >> 5) + (threadIdx.x >> 5);
    if (n >= N) return;
    int lane = threadIdx.x & 31;
    int b = (int)__ldg(&batch[n]);
    if ((unsigned)b >= (unsigned)G) return;
    float4 v = *(const float4*)&g_y[n * HDIM + lane * 4];
    v.x = fmaxf(v.x, 0.f); v.y = fmaxf(v.y, 0.f);
    v.z = fmaxf(v.z, 0.f); v.w = fmaxf(v.w, 0.f);
    float* p = &g_gsum[b * HDIM + lane * 4];
    asm volatile("red.global.add.v4.f32 [%0], {%1,%2,%3,%4};"
                 :: "l"(p), "f"(v.x), "f"(v.y), "f"(v.z), "f"(v.w)
                 : "memory");
    if (lane == 0) atomicAdd(&g_gcnt[b], 1.0f);
}

// Final MLP: single block. g = gsum/cnt; h1 = relu(g@Wl1+bl1); out = h1@Wl2+bl2
__global__ void mlp_kernel(const float* __restrict__ Wl1,
                           const float* __restrict__ bl1,
                           const float* __restrict__ Wl2,
                           const float* __restrict__ bl2,
                           float* __restrict__ out,
                           int G, int H2, int C) {
    __shared__ float sh[4096];   // G*H2 <= 4096
    int tid = threadIdx.x;
    for (int idx = tid; idx < G * H2; idx += blockDim.x) {
        int g = idx / H2, j = idx % H2;
        float inv = 1.0f / fmaxf(g_gcnt[g], 1.0f);
        float s = bl1[j];
        for (int k = 0; k < HDIM; k++)
            s += (g_gsum[g * HDIM + k] * inv) * Wl1[k * H2 + j];
        sh[idx] = fmaxf(s, 0.f);
    }
    __syncthreads();
    for (int idx = tid; idx < G * C; idx += blockDim.x) {
        int g = idx / C, c = idx % C;
        float s = bl2[c];
        for (int j = 0; j < H2; j++)
            s += sh[g * H2 + j] * Wl2[j * C + c];
        out[idx] = s;
    }
}

// ---------------------------------------------------------------------------
extern "C" void kernel_launch(void* const* d_in, const int* in_sizes, int n_in,
                              void* d_out, int out_size) {
    const float* pos  = (const float*)d_in[0];
    const idx_t* ei   = (const idx_t*)d_in[1];
    const idx_t* batch= (const idx_t*)d_in[2];
    const float* W1   = (const float*)d_in[3];
    const float* b1   = (const float*)d_in[4];
    const float* W2   = (const float*)d_in[5];
    const float* b2   = (const float*)d_in[6];
    const float* W3   = (const float*)d_in[7];
    const float* b3   = (const float*)d_in[8];
    const float* Wl1  = (const float*)d_in[9];
    const float* bl1  = (const float*)d_in[10];
    const float* Wl2  = (const float*)d_in[11];
    const float* bl2  = (const float*)d_in[12];
    float* out = (float*)d_out;

    int H  = in_sizes[4];              // 128
    int D  = in_sizes[3] / H;          // 3
    int N  = in_sizes[0] / D;          // 50000
    int E  = in_sizes[1] / 2;          // 800000
    int H2 = in_sizes[10];             // 64
    int C  = in_sizes[12];             // 10
    int G  = out_size / C;             // 64

    int initN = N > G * H ? N : G * H;
    init_kernel<<<(initN + 255) / 256, 256>>>(N, G * H, G);
    deg_kernel<<<(E + 255) / 256, 256>>>(ei, E, N);
    dinv_kernel<<<(N + 255) / 256, 256>>>(N);

    // Layer 1
    dense1_kernel<<<N, H>>>(pos, W1, N, D);
    agg_init_kernel<<<(N * 32 + 255) / 256, 256>>>(b1, N);
    agg_edge_kernel<<<(E + 7) / 8, 256>>>(ei, E, N);

    // Layer 2
    dense_relu_kernel<<<(N + 63) / 64, 256>>>(W2, N);
    agg_init_kernel<<<(N * 32 + 255) / 256, 256>>>(b2, N);
    agg_edge_kernel<<<(E + 7) / 8, 256>>>(ei, E, N);

    // Layer 3
    dense_relu_kernel<<<(N + 63) / 64, 256>>>(W3, N);
    agg_init_kernel<<<(N * 32 + 255) / 256, 256>>>(b3, N);
    agg_edge_kernel<<<(E + 7) / 8, 256>>>(ei, E, N);

    // Pool + MLP
    pool_kernel<<<(N + 7) / 8, 256>>>(batch, N, G);
    mlp_kernel<<<1, 256>>>(Wl1, bl1, Wl2, bl2, out, G, H2, C);
}

// round 2
// speedup vs baseline: 1.5075x; 1.5075x over previous
#include <cuda_runtime.h>

// ---------------------------------------------------------------------------
// GCN 3-layer + mean-pool + MLP for GB300 (sm_103a)   — Round 2: CSR aggregation
// Shape: N=50000, E=800000, D=3, H=128, G=64, H2=64, C=10
// ---------------------------------------------------------------------------

#define HDIM 128
#define MAXN 50176
#define MAXE 850000
#define MAXG 256

typedef int idx_t;   // confirmed int32 in round 1

// Scratch (static device globals; no runtime allocation allowed)
__device__ float g_h[MAXN * HDIM];      // dense output (gather source)
__device__ float g_y[MAXN * HDIM];      // aggregated + relu'd output
__device__ float g_dinv[MAXN];          // deg^-1/2
__device__ int   g_cnt[MAXN];           // in-degree (excl self-loop)
__device__ int   g_cur[MAXN];           // fill cursors
__device__ int   g_off[MAXN];           // CSR row offsets (exclusive)
__device__ int   g_blk[260];            // block sums for scan
__device__ int   g_csr_src[MAXE];       // CSR: source node per edge slot
__device__ float g_csr_nrm[MAXE];       // CSR: dinv[s]*dinv[d] per edge slot
__device__ float g_gsum[MAXG * HDIM];   // per-graph sums
__device__ float g_gcnt[MAXG];          // per-graph counts

// ---------------------------------------------------------------------------
__global__ void setup_kernel(int N, int GH, int G) {
    int i = blockIdx.x * blockDim.x + threadIdx.x;
    if (i < N) { g_cnt[i] = 0; g_cur[i] = 0; }
    if (i < GH) g_gsum[i] = 0.0f;
    if (i < G) g_gcnt[i] = 0.0f;
}

__global__ void hist_kernel(const idx_t* __restrict__ ei, int E, int N) {
    int e = blockIdx.x * blockDim.x + threadIdx.x;
    if (e >= E) return;
    int d = (int)ei[(long long)E + e];
    if ((unsigned)d < (unsigned)N) atomicAdd(&g_cnt[d], 1);
}

__global__ void dinv_kernel(int N) {
    int i = blockIdx.x * blockDim.x + threadIdx.x;
    if (i < N) g_dinv[i] = rsqrtf((float)(g_cnt[i] + 1));  // +1 self-loop
}

// --- 3-kernel exclusive scan of g_cnt -> g_off ------------------------------
__global__ void scan_blocksum(int N) {
    __shared__ int sh[256];
    int t = threadIdx.x;
    int i = blockIdx.x * 256 + t;
    sh[t] = (i < N) ? g_cnt[i] : 0;
    __syncthreads();
    for (int ofs = 128; ofs > 0; ofs >>= 1) {
        if (t < ofs) sh[t] += sh[t + ofs];
        __syncthreads();
    }
    if (t == 0) g_blk[blockIdx.x] = sh[0];
}

__global__ void scan_top(int NB) {
    __shared__ int sh[256];
    int t = threadIdx.x;
    int v = (t < NB) ? g_blk[t] : 0;
    sh[t] = v;
    __syncthreads();
    for (int ofs = 1; ofs < 256; ofs <<= 1) {
        int add = (t >= ofs) ? sh[t - ofs] : 0;
        __syncthreads();
        sh[t] += add;
        __syncthreads();
    }
    if (t < NB) g_blk[t] = sh[t] - v;   // exclusive
}

__global__ void scan_final(int N) {
    __shared__ int sh[256];
    int t = threadIdx.x;
    int i = blockIdx.x * 256 + t;
    int v = (i < N) ? g_cnt[i] : 0;
    sh[t] = v;
    __syncthreads();
    for (int ofs = 1; ofs < 256; ofs <<= 1) {
        int add = (t >= ofs) ? sh[t - ofs] : 0;
        __syncthreads();
        sh[t] += add;
        __syncthreads();
    }
    if (i < N) g_off[i] = g_blk[blockIdx.x] + sh[t] - v;
}

__global__ void edge_fill(const idx_t* __restrict__ ei, int E, int N) {
    int e = blockIdx.x * blockDim.x + threadIdx.x;
    if (e >= E) return;
    int s = (int)ei[e];
    int d = (int)ei[(long long)E + e];
    if ((unsigned)s >= (unsigned)N || (unsigned)d >= (unsigned)N) return;
    int p = g_off[d] + atomicAdd(&g_cur[d], 1);
    g_csr_src[p] = s;
    g_csr_nrm[p] = g_dinv[s] * g_dinv[d];
}

// --- Layer-1 dense: h = pos @ W1 (thread per node x float4) -----------------
__global__ void dense1_kernel(const float* __restrict__ pos,
                              const float* __restrict__ W1, int N, int D) {
    int u = blockIdx.x * blockDim.x + threadIdx.x;
    if (u >= N * 32) return;
    int n = u >> 5, q = u & 31;
    float4 acc = make_float4(0.f, 0.f, 0.f, 0.f);
    for (int d = 0; d < D; d++) {
        float x = __ldg(&pos[n * D + d]);            // broadcast across 32 lanes
        float4 w4 = *(const float4*)&W1[d * HDIM + q * 4];
        acc.x += x * w4.x; acc.y += x * w4.y;
        acc.z += x * w4.z; acc.w += x * w4.w;
    }
    *(float4*)&g_h[n * HDIM + q * 4] = acc;
}

// --- CSR aggregation: warp per dst node -------------------------------------
// y[d] = relu( b + h[d]*dinv[d]^2 + sum_e h[src_e]*nrm_e )
// mode 0: write g_y.  mode 1: fused mean-pool (red into g_gsum, count g_gcnt).
__global__ void __launch_bounds__(256)
agg_csr_kernel(const float* __restrict__ b, int N, int mode,
               const idx_t* __restrict__ batch, int G) {
    int n = blockIdx.x * 8 + (threadIdx.x >> 5);
    if (n >= N) return;
    int lane = threadIdx.x & 31;

    float di = g_dinv[n];
    float w = di * di;
    float4 b4 = *(const float4*)&b[lane * 4];
    float4 h4 = *(const float4*)&g_h[n * HDIM + lane * 4];
    float4 acc;
    acc.x = b4.x + h4.x * w; acc.y = b4.y + h4.y * w;
    acc.z = b4.z + h4.z * w; acc.w = b4.w + h4.w * w;

    int e = g_off[n];
    int end = e + g_cnt[n];
    for (; e + 1 < end; e += 2) {
        int s0 = g_csr_src[e], s1 = g_csr_src[e + 1];
        float n0 = g_csr_nrm[e], n1 = g_csr_nrm[e + 1];
        float4 v0 = *(const float4*)&g_h[s0 * HDIM + lane * 4];
        float4 v1 = *(const float4*)&g_h[s1 * HDIM + lane * 4];
        acc.x += v0.x * n0 + v1.x * n1;
        acc.y += v0.y * n0 + v1.y * n1;
        acc.z += v0.z * n0 + v1.z * n1;
        acc.w += v0.w * n0 + v1.w * n1;
    }
    if (e < end) {
        int s0 = g_csr_src[e];
        float n0 = g_csr_nrm[e];
        float4 v0 = *(const float4*)&g_h[s0 * HDIM + lane * 4];
        acc.x += v0.x * n0; acc.y += v0.y * n0;
        acc.z += v0.z * n0; acc.w += v0.w * n0;
    }

    acc.x = fmaxf(acc.x, 0.f); acc.y = fmaxf(acc.y, 0.f);
    acc.z = fmaxf(acc.z, 0.f); acc.w = fmaxf(acc.w, 0.f);

    if (mode == 0) {
        *(float4*)&g_y[n * HDIM + lane * 4] = acc;
    } else {
        int bg = (int)__ldg(&batch[n]);
        if ((unsigned)bg < (unsigned)G) {
            float* p = &g_gsum[bg * HDIM + lane * 4];
            asm volatile("red.global.add.v4.f32 [%0], {%1,%2,%3,%4};"
                         :: "l"(p), "f"(acc.x), "f"(acc.y), "f"(acc.z), "f"(acc.w)
                         : "memory");
            if (lane == 0) atomicAdd(&g_gcnt[bg], 1.0f);
        }
    }
}

// --- Dense layers 2/3: h = y @ W (y already relu'd) --------------------------
// Block = 256 threads, 64 nodes x 128 cols; thread = 8 nodes x 4 cols.
__global__ void __launch_bounds__(256)
dense_kernel(const float* __restrict__ W, int N) {
    __shared__ float Ws[32 * 128];
    __shared__ float Xs[32 * 65];
    int tid = threadIdx.x;
    int tc = tid & 31;
    int tr = tid >> 5;
    int n0 = blockIdx.x * 64;

    float acc[8][4];
#pragma unroll
    for (int i = 0; i < 8; i++)
#pragma unroll
        for (int j = 0; j < 4; j++) acc[i][j] = 0.0f;

    for (int k0 = 0; k0 < HDIM; k0 += 32) {
        __syncthreads();
#pragma unroll
        for (int t = 0; t < 4; t++) {
            int i = tid + t * 256;
            int kk = i >> 5, cq = i & 31;
            *(float4*)&Ws[kk * 128 + cq * 4] =
                *(const float4*)&W[(k0 + kk) * HDIM + cq * 4];
        }
#pragma unroll
        for (int t = 0; t < 2; t++) {
            int i = tid + t * 256;
            int nn = i >> 3, kq = i & 7;
            int node = n0 + nn;
            float4 v = make_float4(0.f, 0.f, 0.f, 0.f);
            if (node < N)
                v = *(const float4*)&g_y[node * HDIM + k0 + kq * 4];
            Xs[(kq * 4 + 0) * 65 + nn] = v.x;
            Xs[(kq * 4 + 1) * 65 + nn] = v.y;
            Xs[(kq * 4 + 2) * 65 + nn] = v.z;
            Xs[(kq * 4 + 3) * 65 + nn] = v.w;
        }
        __syncthreads();
#pragma unroll
        for (int kk = 0; kk < 32; kk++) {
            float4 w4 = *(float4*)&Ws[kk * 128 + tc * 4];
#pragma unroll
            for (int i = 0; i < 8; i++) {
                float x = Xs[kk * 65 + tr * 8 + i];
                acc[i][0] += x * w4.x;
                acc[i][1] += x * w4.y;
                acc[i][2] += x * w4.z;
                acc[i][3] += x * w4.w;
            }
        }
    }
#pragma unroll
    for (int i = 0; i < 8; i++) {
        int node = n0 + tr * 8 + i;
        if (node < N)
            *(float4*)&g_h[node * HDIM + tc * 4] =
                make_float4(acc[i][0], acc[i][1], acc[i][2], acc[i][3]);
    }
}

// --- Final MLP (single block) ------------------------------------------------
__global__ void mlp_kernel(const float* __restrict__ Wl1,
                           const float* __restrict__ bl1,
                           const float* __restrict__ Wl2,
                           const float* __restrict__ bl2,
                           float* __restrict__ out,
                           int G, int H2, int C) {
    __shared__ float sh[4096];
    int tid = threadIdx.x;
    for (int idx = tid; idx < G * H2; idx += blockDim.x) {
        int g = idx / H2, j = idx % H2;
        float inv = 1.0f / fmaxf(g_gcnt[g], 1.0f);
        float s = bl1[j];
        for (int k = 0; k < HDIM; k++)
            s += (g_gsum[g * HDIM + k] * inv) * Wl1[k * H2 + j];
        sh[idx] = fmaxf(s, 0.f);
    }
    __syncthreads();
    for (int idx = tid; idx < G * C; idx += blockDim.x) {
        int g = idx / C, c = idx % C;
        float s = bl2[c];
        for (int j = 0; j < H2; j++)
            s += sh[g * H2 + j] * Wl2[j * C + c];
        out[idx] = s;
    }
}

// ---------------------------------------------------------------------------
extern "C" void kernel_launch(void* const* d_in, const int* in_sizes, int n_in,
                              void* d_out, int out_size) {
    const float* pos  = (const float*)d_in[0];
    const idx_t* ei   = (const idx_t*)d_in[1];
    const idx_t* batch= (const idx_t*)d_in[2];
    const float* W1   = (const float*)d_in[3];
    const float* b1   = (const float*)d_in[4];
    const float* W2   = (const float*)d_in[5];
    const float* b2   = (const float*)d_in[6];
    const float* W3   = (const float*)d_in[7];
    const float* b3   = (const float*)d_in[8];
    const float* Wl1  = (const float*)d_in[9];
    const float* bl1  = (const float*)d_in[10];
    const float* Wl2  = (const float*)d_in[11];
    const float* bl2  = (const float*)d_in[12];
    float* out = (float*)d_out;

    int H  = in_sizes[4];              // 128
    int D  = in_sizes[3] / H;          // 3
    int N  = in_sizes[0] / D;          // 50000
    int E  = in_sizes[1] / 2;          // 800000
    int H2 = in_sizes[10];             // 64
    int C  = in_sizes[12];             // 10
    int G  = out_size / C;             // 64

    int NB = (N + 255) / 256;          // scan blocks (196)

    int initN = N > G * H ? N : G * H;
    setup_kernel<<<(initN + 255) / 256, 256>>>(N, G * H, G);
    hist_kernel<<<(E + 255) / 256, 256>>>(ei, E, N);
    dinv_kernel<<<NB, 256>>>(N);
    scan_blocksum<<<NB, 256>>>(N);
    scan_top<<<1, 256>>>(NB);
    scan_final<<<NB, 256>>>(N);
    edge_fill<<<(E + 255) / 256, 256>>>(ei, E, N);

    // Layer 1
    dense1_kernel<<<(N * 32 + 255) / 256, 256>>>(pos, W1, N, D);
    agg_csr_kernel<<<(N + 7) / 8, 256>>>(b1, N, 0, batch, G);
    // Layer 2
    dense_kernel<<<(N + 63) / 64, 256>>>(W2, N);
    agg_csr_kernel<<<(N + 7) / 8, 256>>>(b2, N, 0, batch, G);
    // Layer 3 (aggregation fused with mean-pool)
    dense_kernel<<<(N + 63) / 64, 256>>>(W3, N);
    agg_csr_kernel<<<(N + 7) / 8, 256>>>(b3, N, 1, batch, G);

    mlp_kernel<<<1, 256>>>(Wl1, bl1, Wl2, bl2, out, G, H2, C);
}

// round 4
// speedup vs baseline: 2.0993x; 1.3925x over previous
#include <cuda_runtime.h>
#include <cuda_fp16.h>
#include <cstdint>

// ---------------------------------------------------------------------------
// GCN 3-layer + mean-pool + MLP for GB300 (sm_103a) — Round 4
//  * layer-1 aggregation commuted to pos-space (D=3)
//  * fp16 hidden state (gather bandwidth /2)
//  * HMMA (mma.sync.m16n8k16) for dense layers 2/3 — baseline PTX, no tcgen05
// Shape: N=50000, E=800000, D=3, H=128, G=64, H2=64, C=10
// ---------------------------------------------------------------------------

#define HDIM 128
#define MAXN 50176
#define MAXE 850000
#define MAXG 256

typedef int idx_t;

// Scratch
__device__ __half g_y16[MAXN * HDIM];   // GEMM input / agg output (zero past N)
__device__ __half g_h16[MAXN * HDIM];   // GEMM output / gather source
__device__ float g_posagg[MAXN * 4];
__device__ float g_dinv[MAXN];
__device__ int   g_cnt[MAXN];
__device__ int   g_cur[MAXN];
__device__ int   g_off[MAXN];
__device__ int   g_blk[260];
__device__ int   g_csr_src[MAXE];
__device__ float g_csr_nrm[MAXE];
__device__ float g_gsum[MAXG * HDIM];
__device__ float g_gcnt[MAXG];

// --------------------------- PTX helpers (baseline ISA only) ----------------
__device__ __forceinline__ uint32_t smem_u32(const void* p) {
    uint32_t a;
    asm("{ .reg .u64 t; cvta.to.shared.u64 t, %1; cvt.u32.u64 %0, t; }"
        : "=r"(a) : "l"(p));
    return a;
}

__device__ __forceinline__ void ldsm_x4(uint32_t& r0, uint32_t& r1,
                                        uint32_t& r2, uint32_t& r3, uint32_t a) {
    asm volatile("ldmatrix.sync.aligned.m8n8.x4.shared.b16 {%0,%1,%2,%3}, [%4];"
                 : "=r"(r0), "=r"(r1), "=r"(r2), "=r"(r3) : "r"(a));
}

__device__ __forceinline__ void ldsm_x4_t(uint32_t& r0, uint32_t& r1,
                                          uint32_t& r2, uint32_t& r3, uint32_t a) {
    asm volatile("ldmatrix.sync.aligned.m8n8.x4.trans.shared.b16 {%0,%1,%2,%3}, [%4];"
                 : "=r"(r0), "=r"(r1), "=r"(r2), "=r"(r3) : "r"(a));
}

__device__ __forceinline__ void mma16816(float4& c, const uint32_t* a,
                                         uint32_t b0, uint32_t b1) {
    asm volatile("mma.sync.aligned.m16n8k16.row.col.f32.f16.f16.f32 "
                 "{%0,%1,%2,%3}, {%4,%5,%6,%7}, {%8,%9}, {%0,%1,%2,%3};"
                 : "+f"(c.x), "+f"(c.y), "+f"(c.z), "+f"(c.w)
                 : "r"(a[0]), "r"(a[1]), "r"(a[2]), "r"(a[3]),
                   "r"(b0), "r"(b1));
}

// ---------------------------------------------------------------------------
__global__ void setup_kernel(int N, int GH, int G) {
    int i = blockIdx.x * blockDim.x + threadIdx.x;
    if (i < N) { g_cnt[i] = 0; g_cur[i] = 0; }
    if (i < GH) g_gsum[i] = 0.0f;
    if (i < G) g_gcnt[i] = 0.0f;
}

__global__ void hist_kernel(const idx_t* __restrict__ ei, int E, int N) {
    int e = blockIdx.x * blockDim.x + threadIdx.x;
    if (e >= E) return;
    int d = (int)ei[(long long)E + e];
    if ((unsigned)d < (unsigned)N) atomicAdd(&g_cnt[d], 1);
}

__global__ void dinv_kernel(int N) {
    int i = blockIdx.x * blockDim.x + threadIdx.x;
    if (i < N) g_dinv[i] = rsqrtf((float)(g_cnt[i] + 1));
}

__global__ void scan_blocksum(int N) {
    __shared__ int sh[256];
    int t = threadIdx.x;
    int i = blockIdx.x * 256 + t;
    sh[t] = (i < N) ? g_cnt[i] : 0;
    __syncthreads();
    for (int ofs = 128; ofs > 0; ofs >>= 1) {
        if (t < ofs) sh[t] += sh[t + ofs];
        __syncthreads();
    }
    if (t == 0) g_blk[blockIdx.x] = sh[0];
}

__global__ void scan_top(int NB) {
    __shared__ int sh[256];
    int t = threadIdx.x;
    int v = (t < NB) ? g_blk[t] : 0;
    sh[t] = v;
    __syncthreads();
    for (int ofs = 1; ofs < 256; ofs <<= 1) {
        int add = (t >= ofs) ? sh[t - ofs] : 0;
        __syncthreads();
        sh[t] += add;
        __syncthreads();
    }
    if (t < NB) g_blk[t] = sh[t] - v;
}

__global__ void scan_final(int N) {
    __shared__ int sh[256];
    int t = threadIdx.x;
    int i = blockIdx.x * 256 + t;
    int v = (i < N) ? g_cnt[i] : 0;
    sh[t] = v;
    __syncthreads();
    for (int ofs = 1; ofs < 256; ofs <<= 1) {
        int add = (t >= ofs) ? sh[t - ofs] : 0;
        __syncthreads();
        sh[t] += add;
        __syncthreads();
    }
    if (i < N) g_off[i] = g_blk[blockIdx.x] + sh[t] - v;
}

__global__ void edge_fill(const idx_t* __restrict__ ei, int E, int N) {
    int e = blockIdx.x * blockDim.x + threadIdx.x;
    if (e >= E) return;
    int s = (int)ei[e];
    int d = (int)ei[(long long)E + e];
    if ((unsigned)s >= (unsigned)N || (unsigned)d >= (unsigned)N) return;
    int p = g_off[d] + atomicAdd(&g_cur[d], 1);
    g_csr_src[p] = s;
    g_csr_nrm[p] = g_dinv[s] * g_dinv[d];
}

// --- Layer-1 aggregation in pos-space (D=3): warp per node ------------------
__global__ void __launch_bounds__(256)
agg_pos_kernel(const float* __restrict__ pos, int N) {
    int n = blockIdx.x * 8 + (threadIdx.x >> 5);
    if (n >= N) return;
    int lane = threadIdx.x & 31;
    float a0 = 0.f, a1 = 0.f, a2 = 0.f;
    int e0 = g_off[n], end = e0 + g_cnt[n];
    for (int e = e0 + lane; e < end; e += 32) {
        int s = g_csr_src[e];
        float nr = g_csr_nrm[e];
        a0 += pos[s * 3 + 0] * nr;
        a1 += pos[s * 3 + 1] * nr;
        a2 += pos[s * 3 + 2] * nr;
    }
#pragma unroll
    for (int o = 16; o > 0; o >>= 1) {
        a0 += __shfl_down_sync(0xFFFFFFFFu, a0, o);
        a1 += __shfl_down_sync(0xFFFFFFFFu, a1, o);
        a2 += __shfl_down_sync(0xFFFFFFFFu, a2, o);
    }
    if (lane == 0) {
        float di = g_dinv[n];
        float w = di * di;
        g_posagg[n * 4 + 0] = a0 + pos[n * 3 + 0] * w;
        g_posagg[n * 4 + 1] = a1 + pos[n * 3 + 1] * w;
        g_posagg[n * 4 + 2] = a2 + pos[n * 3 + 2] * w;
    }
}

// --- Layer-1 dense: y1 = relu(posagg @ W1 + b1) -> fp16 ---------------------
__global__ void dense1_kernel(const float* __restrict__ W1,
                              const float* __restrict__ b1, int N) {
    int u = blockIdx.x * blockDim.x + threadIdx.x;
    if (u >= N * 32) return;
    int n = u >> 5, q = u & 31;
    float x0 = g_posagg[n * 4 + 0];
    float x1 = g_posagg[n * 4 + 1];
    float x2 = g_posagg[n * 4 + 2];
    float4 w0 = *(const float4*)&W1[0 * HDIM + q * 4];
    float4 w1 = *(const float4*)&W1[1 * HDIM + q * 4];
    float4 w2 = *(const float4*)&W1[2 * HDIM + q * 4];
    float4 b4 = *(const float4*)&b1[q * 4];
    float4 a;
    a.x = fmaxf(b4.x + x0 * w0.x + x1 * w1.x + x2 * w2.x, 0.f);
    a.y = fmaxf(b4.y + x0 * w0.y + x1 * w1.y + x2 * w2.y, 0.f);
    a.z = fmaxf(b4.z + x0 * w0.z + x1 * w1.z + x2 * w2.z, 0.f);
    a.w = fmaxf(b4.w + x0 * w0.w + x1 * w1.w + x2 * w2.w, 0.f);
    __half2 h01 = __floats2half2_rn(a.x, a.y);
    __half2 h23 = __floats2half2_rn(a.z, a.w);
    uint2 o = make_uint2(*(uint32_t*)&h01, *(uint32_t*)&h23);
    *(uint2*)&g_y16[n * HDIM + q * 4] = o;
}

// --- Dense layers 2/3 via HMMA: h16 = y16 @ W  (M=128/blk, N=128, K=128) ----
// 8 warps; warp tile 32x64; K staged in two 64-wide smem chunks.
#define AS_STRIDE 72    // halves per A row (64 + 8 pad) -> +4 bank rot/row
#define BS_STRIDE 136   // halves per B row (128 + 8 pad)

__global__ void __launch_bounds__(256)
dense_mma_kernel(const float* __restrict__ W, int N) {
    __shared__ __half As[128 * AS_STRIDE];   // [row][k]  18KB
    __shared__ __half Bs[64 * BS_STRIDE];    // [k][n]    17KB

    int tid = threadIdx.x;
    int wid = tid >> 5;
    int lane = tid & 31;
    int nb = blockIdx.x * 128;

    int m0 = (wid & 3) * 32;    // warp m offset
    int n0 = (wid >> 2) * 64;   // warp n offset

    float4 acc[2][8];
#pragma unroll
    for (int i = 0; i < 2; i++)
#pragma unroll
        for (int j = 0; j < 8; j++) acc[i][j] = make_float4(0.f, 0.f, 0.f, 0.f);

    for (int c = 0; c < 2; c++) {
        __syncthreads();
        // A chunk: 128 rows x 64 halves (8 uint4/row), 4 uint4 per thread
#pragma unroll
        for (int t = 0; t < 4; t++) {
            int i = tid + t * 256;
            int row = i >> 3, q = i & 3 | ((i & 4) ? 4 : 0);  // q = i & 7
            q = i & 7;
            uint4 v = *(const uint4*)&g_y16[(size_t)(nb + row) * HDIM + c * 64 + q * 8];
            *(uint4*)&As[row * AS_STRIDE + q * 8] = v;
        }
        // B chunk: W rows c*64..+63, 128 cols fp32 -> fp16. 2048 float4 units.
#pragma unroll
        for (int t = 0; t < 8; t++) {
            int i = tid + t * 256;
            int row = i >> 5, c4 = (i & 31) * 4;
            float4 w4 = *(const float4*)&W[(c * 64 + row) * HDIM + c4];
            __half2 h0 = __floats2half2_rn(w4.x, w4.y);
            __half2 h1 = __floats2half2_rn(w4.z, w4.w);
            *(uint2*)&Bs[row * BS_STRIDE + c4] =
                make_uint2(*(uint32_t*)&h0, *(uint32_t*)&h1);
        }
        __syncthreads();

#pragma unroll
        for (int kk = 0; kk < 4; kk++) {
            int k16 = kk * 16;
            // A fragments: 2 m-tiles
            uint32_t af[2][4];
#pragma unroll
            for (int mt = 0; mt < 2; mt++) {
                uint32_t a = smem_u32(
                    &As[(m0 + mt * 16 + (lane & 15)) * AS_STRIDE + k16 + (lane >> 4) * 8]);
                ldsm_x4(af[mt][0], af[mt][1], af[mt][2], af[mt][3], a);
            }
            // B fragments: 4 ldmatrix.x4.trans, each covers n16 (two n8 tiles)
            uint32_t bf[8][2];
#pragma unroll
            for (int nt2 = 0; nt2 < 4; nt2++) {
                uint32_t a = smem_u32(
                    &Bs[(k16 + (lane & 15)) * BS_STRIDE + n0 + nt2 * 16 + (lane >> 4) * 8]);
                uint32_t r0, r1, r2, r3;
                ldsm_x4_t(r0, r1, r2, r3, a);
                bf[nt2 * 2 + 0][0] = r0; bf[nt2 * 2 + 0][1] = r1;
                bf[nt2 * 2 + 1][0] = r2; bf[nt2 * 2 + 1][1] = r3;
            }
#pragma unroll
            for (int mt = 0; mt < 2; mt++)
#pragma unroll
                for (int nt = 0; nt < 8; nt++)
                    mma16816(acc[mt][nt], af[mt], bf[nt][0], bf[nt][1]);
        }
    }

    // Epilogue: c.x,c.y at (row tg, col 2*tp), c.z,c.w at (row tg+8)
    int tg = lane >> 2, tp = lane & 3;
#pragma unroll
    for (int mt = 0; mt < 2; mt++) {
        int r0 = nb + m0 + mt * 16 + tg;
#pragma unroll
        for (int nt = 0; nt < 8; nt++) {
            int col = n0 + nt * 8 + 2 * tp;
            if (r0 < N) {
                __half2 h = __floats2half2_rn(acc[mt][nt].x, acc[mt][nt].y);
                *(__half2*)&g_h16[(size_t)r0 * HDIM + col] = h;
            }
            if (r0 + 8 < N) {
                __half2 h = __floats2half2_rn(acc[mt][nt].z, acc[mt][nt].w);
                *(__half2*)&g_h16[(size_t)(r0 + 8) * HDIM + col] = h;
            }
        }
    }
}

// --- CSR aggregation over fp16 h: warp per node -----------------------------
__global__ void __launch_bounds__(256)
agg16_kernel(const float* __restrict__ b, int N, int mode,
             const idx_t* __restrict__ batch, int G) {
    int n = blockIdx.x * 8 + (threadIdx.x >> 5);
    if (n >= N) return;
    int lane = threadIdx.x & 31;

    float di = g_dinv[n];
    float w = di * di;
    float4 b4 = *(const float4*)&b[lane * 4];

    uint2 hs = *(const uint2*)&g_h16[(size_t)n * HDIM + lane * 4];
    float2 f0 = __half22float2(*(__half2*)&hs.x);
    float2 f1 = __half22float2(*(__half2*)&hs.y);
    float4 acc;
    acc.x = b4.x + f0.x * w; acc.y = b4.y + f0.y * w;
    acc.z = b4.z + f1.x * w; acc.w = b4.w + f1.y * w;

    int e = g_off[n];
    int end = e + g_cnt[n];
    for (; e + 1 < end; e += 2) {
        int s0 = g_csr_src[e], s1 = g_csr_src[e + 1];
        float n0 = g_csr_nrm[e], n1 = g_csr_nrm[e + 1];
        uint2 u0 = *(const uint2*)&g_h16[(size_t)s0 * HDIM + lane * 4];
        uint2 u1 = *(const uint2*)&g_h16[(size_t)s1 * HDIM + lane * 4];
        float2 a0 = __half22float2(*(__half2*)&u0.x);
        float2 a1 = __half22float2(*(__half2*)&u0.y);
        float2 c0 = __half22float2(*(__half2*)&u1.x);
        float2 c1 = __half22float2(*(__half2*)&u1.y);
        acc.x += a0.x * n0 + c0.x * n1;
        acc.y += a0.y * n0 + c0.y * n1;
        acc.z += a1.x * n0 + c1.x * n1;
        acc.w += a1.y * n0 + c1.y * n1;
    }
    if (e < end) {
        int s0 = g_csr_src[e];
        float n0 = g_csr_nrm[e];
        uint2 u0 = *(const uint2*)&g_h16[(size_t)s0 * HDIM + lane * 4];
        float2 a0 = __half22float2(*(__half2*)&u0.x);
        float2 a1 = __half22float2(*(__half2*)&u0.y);
        acc.x += a0.x * n0; acc.y += a0.y * n0;
        acc.z += a1.x * n0; acc.w += a1.y * n0;
    }

    acc.x = fmaxf(acc.x, 0.f); acc.y = fmaxf(acc.y, 0.f);
    acc.z = fmaxf(acc.z, 0.f); acc.w = fmaxf(acc.w, 0.f);

    if (mode == 0) {
        __half2 h01 = __floats2half2_rn(acc.x, acc.y);
        __half2 h23 = __floats2half2_rn(acc.z, acc.w);
        uint2 o = make_uint2(*(uint32_t*)&h01, *(uint32_t*)&h23);
        *(uint2*)&g_y16[(size_t)n * HDIM + lane * 4] = o;
    } else {
        int bg = (int)__ldg(&batch[n]);
        if ((unsigned)bg < (unsigned)G) {
            float* p = &g_gsum[bg * HDIM + lane * 4];
            asm volatile("red.global.add.v4.f32 [%0], {%1,%2,%3,%4};"
                         :: "l"(p), "f"(acc.x), "f"(acc.y), "f"(acc.z), "f"(acc.w)
                         : "memory");
            if (lane == 0) atomicAdd(&g_gcnt[bg], 1.0f);
        }
    }
}

// --- Final MLP (single block) ------------------------------------------------
__global__ void mlp_kernel(const float* __restrict__ Wl1,
                           const float* __restrict__ bl1,
                           const float* __restrict__ Wl2,
                           const float* __restrict__ bl2,
                           float* __restrict__ out,
                           int G, int H2, int C) {
    __shared__ float sh[4096];
    int tid = threadIdx.x;
    for (int idx = tid; idx < G * H2; idx += blockDim.x) {
        int g = idx / H2, j = idx % H2;
        float inv = 1.0f / fmaxf(g_gcnt[g], 1.0f);
        float s = bl1[j];
        for (int k = 0; k < HDIM; k++)
            s += (g_gsum[g * HDIM + k] * inv) * Wl1[k * H2 + j];
        sh[idx] = fmaxf(s, 0.f);
    }
    __syncthreads();
    for (int idx = tid; idx < G * C; idx += blockDim.x) {
        int g = idx / C, c = idx % C;
        float s = bl2[c];
        for (int j = 0; j < H2; j++)
            s += sh[g * H2 + j] * Wl2[j * C + c];
        out[idx] = s;
    }
}

// ---------------------------------------------------------------------------
extern "C" void kernel_launch(void* const* d_in, const int* in_sizes, int n_in,
                              void* d_out, int out_size) {
    const float* pos  = (const float*)d_in[0];
    const idx_t* ei   = (const idx_t*)d_in[1];
    const idx_t* batch= (const idx_t*)d_in[2];
    const float* W1   = (const float*)d_in[3];
    const float* b1   = (const float*)d_in[4];
    const float* W2   = (const float*)d_in[5];
    const float* b2   = (const float*)d_in[6];
    const float* W3   = (const float*)d_in[7];
    const float* b3   = (const float*)d_in[8];
    const float* Wl1  = (const float*)d_in[9];
    const float* bl1  = (const float*)d_in[10];
    const float* Wl2  = (const float*)d_in[11];
    const float* bl2  = (const float*)d_in[12];
    float* out = (float*)d_out;

    int H  = in_sizes[4];              // 128
    int D  = in_sizes[3] / H;          // 3
    int N  = in_sizes[0] / D;          // 50000
    int E  = in_sizes[1] / 2;          // 800000
    int H2 = in_sizes[10];             // 64
    int C  = in_sizes[12];             // 10
    int G  = out_size / C;             // 64

    int NB = (N + 255) / 256;

    int initN = N > G * H ? N : G * H;
    setup_kernel<<<(initN + 255) / 256, 256>>>(N, G * H, G);
    hist_kernel<<<(E + 255) / 256, 256>>>(ei, E, N);
    dinv_kernel<<<NB, 256>>>(N);
    scan_blocksum<<<NB, 256>>>(N);
    scan_top<<<1, 256>>>(NB);
    scan_final<<<NB, 256>>>(N);
    edge_fill<<<(E + 255) / 256, 256>>>(ei, E, N);

    // Layer 1 (aggregation commuted to pos-space)
    agg_pos_kernel<<<(N + 7) / 8, 256>>>(pos, N);
    dense1_kernel<<<(N * 32 + 255) / 256, 256>>>(W1, b1, N);

    // Layer 2
    dense_mma_kernel<<<(N + 127) / 128, 256>>>(W2, N);
    agg16_kernel<<<(N + 7) / 8, 256>>>(b2, N, 0, batch, G);

    // Layer 3 (aggregation fused with mean-pool)
    dense_mma_kernel<<<(N + 127) / 128, 256>>>(W3, N);
    agg16_kernel<<<(N + 7) / 8, 256>>>(b3, N, 1, batch, G);

    mlp_kernel<<<1, 256>>>(Wl1, bl1, Wl2, bl2, out, G, H2, C);
}

// round 6
// speedup vs baseline: 2.1416x; 1.0202x over previous
#include <cuda_runtime.h>
#include <cuda_fp16.h>
#include <cstdint>

// ---------------------------------------------------------------------------
// GCN 3-layer + mean-pool + MLP for GB300 (sm_103a) — Round 6
//  * single-pass scan with PACKED 64-bit (flag,value) lookback state
//    (round-5 crash: flag/val read as two loads -> double-count race ->
//     oversized offsets -> OOB CSR writes -> garbage indices -> illegal access)
//  * fused layer-1 (pos-space aggregation + dense + relu -> fp16)
//  * HMMA dense layers 2/3 with smem-staged coalesced epilogue
//  * fp16 hidden state, CSR warp-per-node aggregation, fused mean-pool
// Shape: N=50000, E=800000, D=3, H=128, G=64, H2=64, C=10
// ---------------------------------------------------------------------------

#define HDIM 128
#define MAXN 50176
#define MAXE 850000
#define MAXG 256

typedef int idx_t;

// Scratch
__device__ __half g_y16[MAXN * HDIM];   // GEMM input / agg output (zero past N)
__device__ __half g_h16[MAXN * HDIM];   // GEMM output / gather source
__device__ float g_dinv[MAXN];
__device__ int   g_cnt[MAXN];
__device__ int   g_cur[MAXN];
__device__ int   g_off[MAXN];
__device__ int   g_csr_src[MAXE];
__device__ float g_csr_nrm[MAXE];
__device__ float g_gsum[MAXG * HDIM];
__device__ float g_gcnt[MAXG];
// decoupled-lookback state: high 32 bits flag (0 none / 1 partial / 2 prefix),
// low 32 bits value. Single 8B load/store => flag+value always consistent.
__device__ unsigned long long g_state[64];

// --------------------------- PTX helpers (baseline ISA only) ----------------
__device__ __forceinline__ uint32_t smem_u32(const void* p) {
    uint32_t a;
    asm("{ .reg .u64 t; cvta.to.shared.u64 t, %1; cvt.u32.u64 %0, t; }"
        : "=r"(a) : "l"(p));
    return a;
}

__device__ __forceinline__ void ldsm_x4(uint32_t& r0, uint32_t& r1,
                                        uint32_t& r2, uint32_t& r3, uint32_t a) {
    asm volatile("ldmatrix.sync.aligned.m8n8.x4.shared.b16 {%0,%1,%2,%3}, [%4];"
                 : "=r"(r0), "=r"(r1), "=r"(r2), "=r"(r3) : "r"(a));
}

__device__ __forceinline__ void ldsm_x4_t(uint32_t& r0, uint32_t& r1,
                                          uint32_t& r2, uint32_t& r3, uint32_t a) {
    asm volatile("ldmatrix.sync.aligned.m8n8.x4.trans.shared.b16 {%0,%1,%2,%3}, [%4];"
                 : "=r"(r0), "=r"(r1), "=r"(r2), "=r"(r3) : "r"(a));
}

__device__ __forceinline__ void mma16816(float4& c, const uint32_t* a,
                                         uint32_t b0, uint32_t b1) {
    asm volatile("mma.sync.aligned.m16n8k16.row.col.f32.f16.f16.f32 "
                 "{%0,%1,%2,%3}, {%4,%5,%6,%7}, {%8,%9}, {%0,%1,%2,%3};"
                 : "+f"(c.x), "+f"(c.y), "+f"(c.z), "+f"(c.w)
                 : "r"(a[0]), "r"(a[1]), "r"(a[2]), "r"(a[3]),
                   "r"(b0), "r"(b1));
}

__device__ __forceinline__ void state_store(int b, unsigned long long v) {
    asm volatile("st.volatile.global.u64 [%0], %1;"
                 :: "l"(&g_state[b]), "l"(v) : "memory");
}

__device__ __forceinline__ unsigned long long state_load(int b) {
    unsigned long long v;
    asm volatile("ld.volatile.global.u64 %0, [%1];"
                 : "=l"(v) : "l"(&g_state[b]) : "memory");
    return v;
}

// ---------------------------------------------------------------------------
__global__ void setup_kernel(int N, int GH, int G) {
    int i = blockIdx.x * blockDim.x + threadIdx.x;
    if (i < N) { g_cnt[i] = 0; g_cur[i] = 0; }
    if (i < GH) g_gsum[i] = 0.0f;
    if (i < G) g_gcnt[i] = 0.0f;
    if (i < 64) g_state[i] = 0ull;
}

__global__ void hist_kernel(const idx_t* __restrict__ ei, int E, int N) {
    int e = blockIdx.x * blockDim.x + threadIdx.x;
    if (e >= E) return;
    int d = (int)ei[(long long)E + e];
    if ((unsigned)d < (unsigned)N) atomicAdd(&g_cnt[d], 1);
}

// --- single-pass decoupled-lookback exclusive scan of g_cnt -> g_off --------
// Also computes g_dinv = rsqrt(cnt+1). 1024 threads x 4 elems per block.
#define SCAN_T 4
#define SCAN_CHUNK 4096

__global__ void __launch_bounds__(1024)
scan_kernel(int N) {
    __shared__ int warp_sums[32];
    __shared__ int s_base;
    int b = blockIdx.x, t = threadIdx.x;
    int base = b * SCAN_CHUNK + t * SCAN_T;

    int v[SCAN_T];
    int sum = 0;
#pragma unroll
    for (int i = 0; i < SCAN_T; i++) {
        int idx = base + i;
        v[i] = (idx < N) ? g_cnt[idx] : 0;
        sum += v[i];
    }
    int lane = t & 31, wid = t >> 5;
    int x = sum;
#pragma unroll
    for (int o = 1; o < 32; o <<= 1) {
        int y = __shfl_up_sync(0xFFFFFFFFu, x, o);
        if (lane >= o) x += y;
    }
    if (lane == 31) warp_sums[wid] = x;
    __syncthreads();
    if (wid == 0) {
        int y = warp_sums[lane];
#pragma unroll
        for (int o = 1; o < 32; o <<= 1) {
            int z = __shfl_up_sync(0xFFFFFFFFu, y, o);
            if (lane >= o) y += z;
        }
        warp_sums[lane] = y;
    }
    __syncthreads();
    int thread_excl = x - sum + (wid > 0 ? warp_sums[wid - 1] : 0);
    int block_total = warp_sums[31];

    if (t == 0) {
        if (b == 0) {
            s_base = 0;
            state_store(0, (2ull << 32) | (unsigned)block_total);
        } else {
            state_store(b, (1ull << 32) | (unsigned)block_total);
            int excl = 0;
            for (int j = b - 1; j >= 0;) {
                unsigned long long st;
                do { st = state_load(j); } while ((st >> 32) == 0);
                excl += (int)(unsigned)st;
                if ((st >> 32) == 2ull) break;
                j--;
            }
            s_base = excl;
            state_store(b, (2ull << 32) | (unsigned)(excl + block_total));
        }
    }
    __syncthreads();

    int off = s_base + thread_excl;
#pragma unroll
    for (int i = 0; i < SCAN_T; i++) {
        int idx = base + i;
        if (idx < N) {
            g_off[idx] = off;
            off += v[i];
            g_dinv[idx] = rsqrtf((float)(v[i] + 1));
        }
    }
}

__global__ void edge_fill(const idx_t* __restrict__ ei, int E, int N) {
    int e = blockIdx.x * blockDim.x + threadIdx.x;
    if (e >= E) return;
    int s = (int)ei[e];
    int d = (int)ei[(long long)E + e];
    if ((unsigned)s >= (unsigned)N || (unsigned)d >= (unsigned)N) return;
    int p = g_off[d] + atomicAdd(&g_cur[d], 1);
    if (p < MAXE) {            // belt-and-braces: degrade to wrong-answer, not UB
        g_csr_src[p] = s;
        g_csr_nrm[p] = g_dinv[s] * g_dinv[d];
    }
}

// --- Fused layer 1: pos-space aggregation + dense + relu -> fp16 ------------
__global__ void __launch_bounds__(256)
layer1_kernel(const float* __restrict__ pos,
              const float* __restrict__ W1,
              const float* __restrict__ b1, int N) {
    int n = blockIdx.x * 8 + (threadIdx.x >> 5);
    if (n >= N) return;
    int lane = threadIdx.x & 31;

    float a0 = 0.f, a1 = 0.f, a2 = 0.f;
    int e0 = g_off[n], end = e0 + g_cnt[n];
    for (int e = e0 + lane; e < end; e += 32) {
        int s = g_csr_src[e];
        float nr = g_csr_nrm[e];
        a0 += pos[s * 3 + 0] * nr;
        a1 += pos[s * 3 + 1] * nr;
        a2 += pos[s * 3 + 2] * nr;
    }
#pragma unroll
    for (int o = 16; o > 0; o >>= 1) {
        a0 += __shfl_down_sync(0xFFFFFFFFu, a0, o);
        a1 += __shfl_down_sync(0xFFFFFFFFu, a1, o);
        a2 += __shfl_down_sync(0xFFFFFFFFu, a2, o);
    }
    float di = g_dinv[n];
    float w = di * di;
    float x0 = __shfl_sync(0xFFFFFFFFu, a0, 0) + pos[n * 3 + 0] * w;
    float x1 = __shfl_sync(0xFFFFFFFFu, a1, 0) + pos[n * 3 + 1] * w;
    float x2 = __shfl_sync(0xFFFFFFFFu, a2, 0) + pos[n * 3 + 2] * w;

    int q = lane;
    float4 w0 = *(const float4*)&W1[0 * HDIM + q * 4];
    float4 w1 = *(const float4*)&W1[1 * HDIM + q * 4];
    float4 w2 = *(const float4*)&W1[2 * HDIM + q * 4];
    float4 b4 = *(const float4*)&b1[q * 4];
    float4 a;
    a.x = fmaxf(b4.x + x0 * w0.x + x1 * w1.x + x2 * w2.x, 0.f);
    a.y = fmaxf(b4.y + x0 * w0.y + x1 * w1.y + x2 * w2.y, 0.f);
    a.z = fmaxf(b4.z + x0 * w0.z + x1 * w1.z + x2 * w2.z, 0.f);
    a.w = fmaxf(b4.w + x0 * w0.w + x1 * w1.w + x2 * w2.w, 0.f);
    __half2 h01 = __floats2half2_rn(a.x, a.y);
    __half2 h23 = __floats2half2_rn(a.z, a.w);
    *(uint2*)&g_y16[(size_t)n * HDIM + q * 4] =
        make_uint2(*(uint32_t*)&h01, *(uint32_t*)&h23);
}

// --- Dense layers 2/3 via HMMA: h16 = y16 @ W  (128x128x128 per block) ------
#define AS_STRIDE 72    // halves per A row (64 + 8 pad)
#define BS_STRIDE 136   // halves per B row (128 + 8 pad)
#define CS_STRIDE 136   // halves per C row for staged epilogue (16B-aligned)

__global__ void __launch_bounds__(256)
dense_mma_kernel(const float* __restrict__ W, int N) {
    __shared__ __align__(16) char smraw[(128 * AS_STRIDE + 64 * BS_STRIDE) * 2];
    __half* As = (__half*)smraw;                     // 128 x 72
    __half* Bs = As + 128 * AS_STRIDE;               // 64 x 136
    __half* Cs = (__half*)smraw;                     // 128 x 136 (reuse, 34816B)

    int tid = threadIdx.x;
    int wid = tid >> 5;
    int lane = tid & 31;
    int nb = blockIdx.x * 128;

    int m0 = (wid & 3) * 32;
    int n0 = (wid >> 2) * 64;

    float4 acc[2][8];
#pragma unroll
    for (int i = 0; i < 2; i++)
#pragma unroll
        for (int j = 0; j < 8; j++) acc[i][j] = make_float4(0.f, 0.f, 0.f, 0.f);

    for (int c = 0; c < 2; c++) {
        __syncthreads();
        // A chunk: 128 rows x 64 halves (8 uint4/row)
#pragma unroll
        for (int t = 0; t < 4; t++) {
            int i = tid + t * 256;
            int row = i >> 3, q = i & 7;
            uint4 v = *(const uint4*)&g_y16[(size_t)(nb + row) * HDIM + c * 64 + q * 8];
            *(uint4*)&As[row * AS_STRIDE + q * 8] = v;
        }
        // B chunk: W rows c*64..+63, 128 cols fp32 -> fp16
#pragma unroll
        for (int t = 0; t < 8; t++) {
            int i = tid + t * 256;
            int row = i >> 5, c4 = (i & 31) * 4;
            float4 w4 = *(const float4*)&W[(c * 64 + row) * HDIM + c4];
            __half2 h0 = __floats2half2_rn(w4.x, w4.y);
            __half2 h1 = __floats2half2_rn(w4.z, w4.w);
            *(uint2*)&Bs[row * BS_STRIDE + c4] =
                make_uint2(*(uint32_t*)&h0, *(uint32_t*)&h1);
        }
        __syncthreads();

#pragma unroll
        for (int kk = 0; kk < 4; kk++) {
            int k16 = kk * 16;
            uint32_t af[2][4];
#pragma unroll
            for (int mt = 0; mt < 2; mt++) {
                uint32_t a = smem_u32(
                    &As[(m0 + mt * 16 + (lane & 15)) * AS_STRIDE + k16 + (lane >> 4) * 8]);
                ldsm_x4(af[mt][0], af[mt][1], af[mt][2], af[mt][3], a);
            }
            uint32_t bf[8][2];
#pragma unroll
            for (int nt2 = 0; nt2 < 4; nt2++) {
                uint32_t a = smem_u32(
                    &Bs[(k16 + (lane & 15)) * BS_STRIDE + n0 + nt2 * 16 + (lane >> 4) * 8]);
                uint32_t r0, r1, r2, r3;
                ldsm_x4_t(r0, r1, r2, r3, a);
                bf[nt2 * 2 + 0][0] = r0; bf[nt2 * 2 + 0][1] = r1;
                bf[nt2 * 2 + 1][0] = r2; bf[nt2 * 2 + 1][1] = r3;
            }
#pragma unroll
            for (int mt = 0; mt < 2; mt++)
#pragma unroll
                for (int nt = 0; nt < 8; nt++)
                    mma16816(acc[mt][nt], af[mt], bf[nt][0], bf[nt][1]);
        }
    }

    // Staged epilogue: fp32 acc -> fp16 into smem, then coalesced 16B stores.
    __syncthreads();
    int tg = lane >> 2, tp = lane & 3;
#pragma unroll
    for (int mt = 0; mt < 2; mt++) {
        int r0 = m0 + mt * 16 + tg;
#pragma unroll
        for (int nt = 0; nt < 8; nt++) {
            int col = n0 + nt * 8 + 2 * tp;
            __half2 hA = __floats2half2_rn(acc[mt][nt].x, acc[mt][nt].y);
            __half2 hB = __floats2half2_rn(acc[mt][nt].z, acc[mt][nt].w);
            *(__half2*)&Cs[r0 * CS_STRIDE + col] = hA;
            *(__half2*)&Cs[(r0 + 8) * CS_STRIDE + col] = hB;
        }
    }
    __syncthreads();
    // 128 rows x 16 uint4 = 2048 units; 8 per thread; coalesced global stores.
#pragma unroll
    for (int t = 0; t < 8; t++) {
        int i = tid + t * 256;
        int row = i >> 4, q = i & 15;
        int node = nb + row;
        if (node < N) {
            uint4 v = *(const uint4*)&Cs[row * CS_STRIDE + q * 8];
            *(uint4*)&g_h16[(size_t)node * HDIM + q * 8] = v;
        }
    }
}

// --- CSR aggregation over fp16 h: warp per node -----------------------------
__global__ void __launch_bounds__(256)
agg16_kernel(const float* __restrict__ b, int N, int mode,
             const idx_t* __restrict__ batch, int G) {
    int n = blockIdx.x * 8 + (threadIdx.x >> 5);
    if (n >= N) return;
    int lane = threadIdx.x & 31;

    float di = g_dinv[n];
    float w = di * di;
    float4 b4 = *(const float4*)&b[lane * 4];

    uint2 hs = *(const uint2*)&g_h16[(size_t)n * HDIM + lane * 4];
    float2 f0 = __half22float2(*(__half2*)&hs.x);
    float2 f1 = __half22float2(*(__half2*)&hs.y);
    float4 acc;
    acc.x = b4.x + f0.x * w; acc.y = b4.y + f0.y * w;
    acc.z = b4.z + f1.x * w; acc.w = b4.w + f1.y * w;

    int e = g_off[n];
    int end = e + g_cnt[n];
    for (; e + 1 < end; e += 2) {
        int s0 = g_csr_src[e], s1 = g_csr_src[e + 1];
        float n0 = g_csr_nrm[e], n1 = g_csr_nrm[e + 1];
        uint2 u0 = *(const uint2*)&g_h16[(size_t)s0 * HDIM + lane * 4];
        uint2 u1 = *(const uint2*)&g_h16[(size_t)s1 * HDIM + lane * 4];
        float2 a0 = __half22float2(*(__half2*)&u0.x);
        float2 a1 = __half22float2(*(__half2*)&u0.y);
        float2 c0 = __half22float2(*(__half2*)&u1.x);
        float2 c1 = __half22float2(*(__half2*)&u1.y);
        acc.x += a0.x * n0 + c0.x * n1;
        acc.y += a0.y * n0 + c0.y * n1;
        acc.z += a1.x * n0 + c1.x * n1;
        acc.w += a1.y * n0 + c1.y * n1;
    }
    if (e < end) {
        int s0 = g_csr_src[e];
        float n0 = g_csr_nrm[e];
        uint2 u0 = *(const uint2*)&g_h16[(size_t)s0 * HDIM + lane * 4];
        float2 a0 = __half22float2(*(__half2*)&u0.x);
        float2 a1 = __half22float2(*(__half2*)&u0.y);
        acc.x += a0.x * n0; acc.y += a0.y * n0;
        acc.z += a1.x * n0; acc.w += a1.y * n0;
    }

    acc.x = fmaxf(acc.x, 0.f); acc.y = fmaxf(acc.y, 0.f);
    acc.z = fmaxf(acc.z, 0.f); acc.w = fmaxf(acc.w, 0.f);

    if (mode == 0) {
        __half2 h01 = __floats2half2_rn(acc.x, acc.y);
        __half2 h23 = __floats2half2_rn(acc.z, acc.w);
        *(uint2*)&g_y16[(size_t)n * HDIM + lane * 4] =
            make_uint2(*(uint32_t*)&h01, *(uint32_t*)&h23);
    } else {
        int bg = (int)__ldg(&batch[n]);
        if ((unsigned)bg < (unsigned)G) {
            float* p = &g_gsum[bg * HDIM + lane * 4];
            asm volatile("red.global.add.v4.f32 [%0], {%1,%2,%3,%4};"
                         :: "l"(p), "f"(acc.x), "f"(acc.y), "f"(acc.z), "f"(acc.w)
                         : "memory");
            if (lane == 0) atomicAdd(&g_gcnt[bg], 1.0f);
        }
    }
}

// --- Final MLP (single block) ------------------------------------------------
__global__ void mlp_kernel(const float* __restrict__ Wl1,
                           const float* __restrict__ bl1,
                           const float* __restrict__ Wl2,
                           const float* __restrict__ bl2,
                           float* __restrict__ out,
                           int G, int H2, int C) {
    __shared__ float sh[4096];
    int tid = threadIdx.x;
    for (int idx = tid; idx < G * H2; idx += blockDim.x) {
        int g = idx / H2, j = idx % H2;
        float inv = 1.0f / fmaxf(g_gcnt[g], 1.0f);
        float s = bl1[j];
        for (int k = 0; k < HDIM; k++)
            s += (g_gsum[g * HDIM + k] * inv) * Wl1[k * H2 + j];
        sh[idx] = fmaxf(s, 0.f);
    }
    __syncthreads();
    for (int idx = tid; idx < G * C; idx += blockDim.x) {
        int g = idx / C, c = idx % C;
        float s = bl2[c];
        for (int j = 0; j < H2; j++)
            s += sh[g * H2 + j] * Wl2[j * C + c];
        out[idx] = s;
    }
}

// ---------------------------------------------------------------------------
extern "C" void kernel_launch(void* const* d_in, const int* in_sizes, int n_in,
                              void* d_out, int out_size) {
    const float* pos  = (const float*)d_in[0];
    const idx_t* ei   = (const idx_t*)d_in[1];
    const idx_t* batch= (const idx_t*)d_in[2];
    const float* W1   = (const float*)d_in[3];
    const float* b1   = (const float*)d_in[4];
    const float* W2   = (const float*)d_in[5];
    const float* b2   = (const float*)d_in[6];
    const float* W3   = (const float*)d_in[7];
    const float* b3   = (const float*)d_in[8];
    const float* Wl1  = (const float*)d_in[9];
    const float* bl1  = (const float*)d_in[10];
    const float* Wl2  = (const float*)d_in[11];
    const float* bl2  = (const float*)d_in[12];
    float* out = (float*)d_out;

    int H  = in_sizes[4];              // 128
    int D  = in_sizes[3] / H;          // 3
    int N  = in_sizes[0] / D;          // 50000
    int E  = in_sizes[1] / 2;          // 800000
    int H2 = in_sizes[10];             // 64
    int C  = in_sizes[12];             // 10
    int G  = out_size / C;             // 64

    int initN = N > G * H ? N : G * H;
    setup_kernel<<<(initN + 255) / 256, 256>>>(N, G * H, G);
    hist_kernel<<<(E + 255) / 256, 256>>>(ei, E, N);
    scan_kernel<<<(N + SCAN_CHUNK - 1) / SCAN_CHUNK, 1024>>>(N);
    edge_fill<<<(E + 255) / 256, 256>>>(ei, E, N);

    // Layer 1 (fused: pos-space aggregation + dense + relu)
    layer1_kernel<<<(N + 7) / 8, 256>>>(pos, W1, b1, N);

    // Layer 2
    dense_mma_kernel<<<(N + 127) / 128, 256>>>(W2, N);
    agg16_kernel<<<(N + 7) / 8, 256>>>(b2, N, 0, batch, G);

    // Layer 3 (aggregation fused with mean-pool)
    dense_mma_kernel<<<(N + 127) / 128, 256>>>(W3, N);
    agg16_kernel<<<(N + 7) / 8, 256>>>(b3, N, 1, batch, G);

    mlp_kernel<<<1, 256>>>(Wl1, bl1, Wl2, bl2, out, G, H2, C);
}

// round 8
// speedup vs baseline: 2.1969x; 1.0258x over previous
#include <cuda_runtime.h>
#include <cuda_fp16.h>
#include <cstdint>

// ---------------------------------------------------------------------------
// GCN 3-layer + mean-pool + MLP for GB300 (sm_103a) — Round 8
//  * FIX round-7 rel_err=1.0: __device__ weight arrays were passed as kernel
//    args from host (host-side symbol value != device address). Kernel now
//    selects g_w2h/g_w3h internally via an int layer argument.
//  * rank-from-histogram CSR build (no cursor atomics in edge_fill)
//  * packed (src, nrm) int2 CSR payload (one 8B scattered store per edge)
//  * W2/W3 pre-converted to fp16 once (halves GEMM weight traffic)
//  * fused layer-1, HMMA dense, fp16 hidden state, fused mean-pool
// Shape: N=50000, E=800000, D=3, H=128, G=64, H2=64, C=10
// ---------------------------------------------------------------------------

#define HDIM 128
#define MAXN 50176
#define MAXE 850000
#define MAXG 256

typedef int idx_t;

// Scratch
__device__ __half g_y16[MAXN * HDIM];   // GEMM input / agg output (zero past N)
__device__ __half g_h16[MAXN * HDIM];   // GEMM output / gather source
__device__ __half g_w2h[HDIM * HDIM];   // W2 in fp16
__device__ __half g_w3h[HDIM * HDIM];   // W3 in fp16
__device__ float g_dinv[MAXN];
__device__ int   g_cnt[MAXN];
__device__ int   g_rank[MAXE];          // edge rank within its dst
__device__ int   g_off[MAXN];
__device__ int2  g_csr[MAXE];           // {src, nrm as bits}
__device__ float g_gsum[MAXG * HDIM];
__device__ float g_gcnt[MAXG];
// decoupled-lookback state: hi 32 = flag (0/1/2), lo 32 = value; single 8B op.
__device__ unsigned long long g_state[64];

// --------------------------- PTX helpers (baseline ISA only) ----------------
__device__ __forceinline__ uint32_t smem_u32(const void* p) {
    uint32_t a;
    asm("{ .reg .u64 t; cvta.to.shared.u64 t, %1; cvt.u32.u64 %0, t; }"
        : "=r"(a) : "l"(p));
    return a;
}

__device__ __forceinline__ void ldsm_x4(uint32_t& r0, uint32_t& r1,
                                        uint32_t& r2, uint32_t& r3, uint32_t a) {
    asm volatile("ldmatrix.sync.aligned.m8n8.x4.shared.b16 {%0,%1,%2,%3}, [%4];"
                 : "=r"(r0), "=r"(r1), "=r"(r2), "=r"(r3) : "r"(a));
}

__device__ __forceinline__ void ldsm_x4_t(uint32_t& r0, uint32_t& r1,
                                          uint32_t& r2, uint32_t& r3, uint32_t a) {
    asm volatile("ldmatrix.sync.aligned.m8n8.x4.trans.shared.b16 {%0,%1,%2,%3}, [%4];"
                 : "=r"(r0), "=r"(r1), "=r"(r2), "=r"(r3) : "r"(a));
}

__device__ __forceinline__ void mma16816(float4& c, const uint32_t* a,
                                         uint32_t b0, uint32_t b1) {
    asm volatile("mma.sync.aligned.m16n8k16.row.col.f32.f16.f16.f32 "
                 "{%0,%1,%2,%3}, {%4,%5,%6,%7}, {%8,%9}, {%0,%1,%2,%3};"
                 : "+f"(c.x), "+f"(c.y), "+f"(c.z), "+f"(c.w)
                 : "r"(a[0]), "r"(a[1]), "r"(a[2]), "r"(a[3]),
                   "r"(b0), "r"(b1));
}

__device__ __forceinline__ void state_store(int b, unsigned long long v) {
    asm volatile("st.volatile.global.u64 [%0], %1;"
                 :: "l"(&g_state[b]), "l"(v) : "memory");
}

__device__ __forceinline__ unsigned long long state_load(int b) {
    unsigned long long v;
    asm volatile("ld.volatile.global.u64 %0, [%1];"
                 : "=l"(v) : "l"(&g_state[b]) : "memory");
    return v;
}

// ---------------------------------------------------------------------------
__global__ void setup_kernel(int N, int GH, int G) {
    int i = blockIdx.x * blockDim.x + threadIdx.x;
    if (i < N) g_cnt[i] = 0;
    if (i < GH) g_gsum[i] = 0.0f;
    if (i < G) g_gcnt[i] = 0.0f;
    if (i < 64) g_state[i] = 0ull;
}

// W2/W3 -> fp16 (independent of graph topology; launched early)
__global__ void wconv_kernel(const float* __restrict__ W2,
                             const float* __restrict__ W3) {
    int i = blockIdx.x * blockDim.x + threadIdx.x;
    if (i < HDIM * HDIM) {
        g_w2h[i] = __float2half(W2[i]);
        g_w3h[i] = __float2half(W3[i]);
    }
}

// Histogram + edge rank (atomicAdd's return value = unique slot within dst)
__global__ void hist_kernel(const idx_t* __restrict__ ei, int E, int N) {
    int e = blockIdx.x * blockDim.x + threadIdx.x;
    if (e >= E) return;
    int d = (int)ei[(long long)E + e];
    int r = 0;
    if ((unsigned)d < (unsigned)N) r = atomicAdd(&g_cnt[d], 1);
    g_rank[e] = r;
}

// --- single-pass decoupled-lookback exclusive scan of g_cnt -> g_off --------
#define SCAN_T 4
#define SCAN_CHUNK 4096

__global__ void __launch_bounds__(1024)
scan_kernel(int N) {
    __shared__ int warp_sums[32];
    __shared__ int s_base;
    int b = blockIdx.x, t = threadIdx.x;
    int base = b * SCAN_CHUNK + t * SCAN_T;

    int v[SCAN_T];
    int sum = 0;
#pragma unroll
    for (int i = 0; i < SCAN_T; i++) {
        int idx = base + i;
        v[i] = (idx < N) ? g_cnt[idx] : 0;
        sum += v[i];
    }
    int lane = t & 31, wid = t >> 5;
    int x = sum;
#pragma unroll
    for (int o = 1; o < 32; o <<= 1) {
        int y = __shfl_up_sync(0xFFFFFFFFu, x, o);
        if (lane >= o) x += y;
    }
    if (lane == 31) warp_sums[wid] = x;
    __syncthreads();
    if (wid == 0) {
        int y = warp_sums[lane];
#pragma unroll
        for (int o = 1; o < 32; o <<= 1) {
            int z = __shfl_up_sync(0xFFFFFFFFu, y, o);
            if (lane >= o) y += z;
        }
        warp_sums[lane] = y;
    }
    __syncthreads();
    int thread_excl = x - sum + (wid > 0 ? warp_sums[wid - 1] : 0);
    int block_total = warp_sums[31];

    if (t == 0) {
        if (b == 0) {
            s_base = 0;
            state_store(0, (2ull << 32) | (unsigned)block_total);
        } else {
            state_store(b, (1ull << 32) | (unsigned)block_total);
            int excl = 0;
            for (int j = b - 1; j >= 0;) {
                unsigned long long st;
                do { st = state_load(j); } while ((st >> 32) == 0);
                excl += (int)(unsigned)st;
                if ((st >> 32) == 2ull) break;
                j--;
            }
            s_base = excl;
            state_store(b, (2ull << 32) | (unsigned)(excl + block_total));
        }
    }
    __syncthreads();

    int off = s_base + thread_excl;
#pragma unroll
    for (int i = 0; i < SCAN_T; i++) {
        int idx = base + i;
        if (idx < N) {
            g_off[idx] = off;
            off += v[i];
            g_dinv[idx] = rsqrtf((float)(v[i] + 1));
        }
    }
}

// CSR fill: slot = off[d] + precomputed rank; one 8B scattered store per edge.
__global__ void edge_fill(const idx_t* __restrict__ ei, int E, int N) {
    int e = blockIdx.x * blockDim.x + threadIdx.x;
    if (e >= E) return;
    int s = (int)ei[e];
    int d = (int)ei[(long long)E + e];
    if ((unsigned)s >= (unsigned)N || (unsigned)d >= (unsigned)N) return;
    int p = g_off[d] + g_rank[e];
    if (p < MAXE) {            // belt-and-braces: degrade to wrong-answer, not UB
        float nr = g_dinv[s] * g_dinv[d];
        g_csr[p] = make_int2(s, __float_as_int(nr));
    }
}

// --- Fused layer 1: pos-space aggregation + dense + relu -> fp16 ------------
__global__ void __launch_bounds__(256)
layer1_kernel(const float* __restrict__ pos,
              const float* __restrict__ W1,
              const float* __restrict__ b1, int N) {
    int n = blockIdx.x * 8 + (threadIdx.x >> 5);
    if (n >= N) return;
    int lane = threadIdx.x & 31;

    float a0 = 0.f, a1 = 0.f, a2 = 0.f;
    int e0 = g_off[n], end = e0 + g_cnt[n];
    for (int e = e0 + lane; e < end; e += 32) {
        int2 c = g_csr[e];
        int s = c.x;
        float nr = __int_as_float(c.y);
        a0 += pos[s * 3 + 0] * nr;
        a1 += pos[s * 3 + 1] * nr;
        a2 += pos[s * 3 + 2] * nr;
    }
#pragma unroll
    for (int o = 16; o > 0; o >>= 1) {
        a0 += __shfl_down_sync(0xFFFFFFFFu, a0, o);
        a1 += __shfl_down_sync(0xFFFFFFFFu, a1, o);
        a2 += __shfl_down_sync(0xFFFFFFFFu, a2, o);
    }
    float di = g_dinv[n];
    float w = di * di;
    float x0 = __shfl_sync(0xFFFFFFFFu, a0, 0) + pos[n * 3 + 0] * w;
    float x1 = __shfl_sync(0xFFFFFFFFu, a1, 0) + pos[n * 3 + 1] * w;
    float x2 = __shfl_sync(0xFFFFFFFFu, a2, 0) + pos[n * 3 + 2] * w;

    int q = lane;
    float4 w0 = *(const float4*)&W1[0 * HDIM + q * 4];
    float4 w1 = *(const float4*)&W1[1 * HDIM + q * 4];
    float4 w2 = *(const float4*)&W1[2 * HDIM + q * 4];
    float4 b4 = *(const float4*)&b1[q * 4];
    float4 a;
    a.x = fmaxf(b4.x + x0 * w0.x + x1 * w1.x + x2 * w2.x, 0.f);
    a.y = fmaxf(b4.y + x0 * w0.y + x1 * w1.y + x2 * w2.y, 0.f);
    a.z = fmaxf(b4.z + x0 * w0.z + x1 * w1.z + x2 * w2.z, 0.f);
    a.w = fmaxf(b4.w + x0 * w0.w + x1 * w1.w + x2 * w2.w, 0.f);
    __half2 h01 = __floats2half2_rn(a.x, a.y);
    __half2 h23 = __floats2half2_rn(a.z, a.w);
    *(uint2*)&g_y16[(size_t)n * HDIM + q * 4] =
        make_uint2(*(uint32_t*)&h01, *(uint32_t*)&h23);
}

// --- Dense layers 2/3 via HMMA: h16 = y16 @ Wh (128x128x128 per block) ------
// layer selects the device-resident fp16 weight array (NOT passed from host).
#define AS_STRIDE 72    // halves per A row (64 + 8 pad)
#define BS_STRIDE 136   // halves per B row (128 + 8 pad)
#define CS_STRIDE 136   // halves per C row for staged epilogue

__global__ void __launch_bounds__(256)
dense_mma_kernel(int layer, int N) {
    const __half* __restrict__ Wh = (layer == 2) ? g_w2h : g_w3h;

    __shared__ __align__(16) char smraw[(128 * AS_STRIDE + 64 * BS_STRIDE) * 2];
    __half* As = (__half*)smraw;                     // 128 x 72
    __half* Bs = As + 128 * AS_STRIDE;               // 64 x 136
    __half* Cs = (__half*)smraw;                     // 128 x 136 (reuse)

    int tid = threadIdx.x;
    int wid = tid >> 5;
    int lane = tid & 31;
    int nb = blockIdx.x * 128;

    int m0 = (wid & 3) * 32;
    int n0 = (wid >> 2) * 64;

    float4 acc[2][8];
#pragma unroll
    for (int i = 0; i < 2; i++)
#pragma unroll
        for (int j = 0; j < 8; j++) acc[i][j] = make_float4(0.f, 0.f, 0.f, 0.f);

    for (int c = 0; c < 2; c++) {
        __syncthreads();
        // A chunk: 128 rows x 64 halves (8 uint4/row)
#pragma unroll
        for (int t = 0; t < 4; t++) {
            int i = tid + t * 256;
            int row = i >> 3, q = i & 7;
            uint4 v = *(const uint4*)&g_y16[(size_t)(nb + row) * HDIM + c * 64 + q * 8];
            *(uint4*)&As[row * AS_STRIDE + q * 8] = v;
        }
        // B chunk (fp16): rows c*64..+63, 128 halves/row = 16 uint4/row
#pragma unroll
        for (int t = 0; t < 4; t++) {
            int i = tid + t * 256;
            int row = i >> 4, q = i & 15;
            uint4 v = *(const uint4*)&Wh[(size_t)(c * 64 + row) * HDIM + q * 8];
            *(uint4*)&Bs[row * BS_STRIDE + q * 8] = v;
        }
        __syncthreads();

#pragma unroll
        for (int kk = 0; kk < 4; kk++) {
            int k16 = kk * 16;
            uint32_t af[2][4];
#pragma unroll
            for (int mt = 0; mt < 2; mt++) {
                uint32_t a = smem_u32(
                    &As[(m0 + mt * 16 + (lane & 15)) * AS_STRIDE + k16 + (lane >> 4) * 8]);
                ldsm_x4(af[mt][0], af[mt][1], af[mt][2], af[mt][3], a);
            }
            uint32_t bf[8][2];
#pragma unroll
            for (int nt2 = 0; nt2 < 4; nt2++) {
                uint32_t a = smem_u32(
                    &Bs[(k16 + (lane & 15)) * BS_STRIDE + n0 + nt2 * 16 + (lane >> 4) * 8]);
                uint32_t r0, r1, r2, r3;
                ldsm_x4_t(r0, r1, r2, r3, a);
                bf[nt2 * 2 + 0][0] = r0; bf[nt2 * 2 + 0][1] = r1;
                bf[nt2 * 2 + 1][0] = r2; bf[nt2 * 2 + 1][1] = r3;
            }
#pragma unroll
            for (int mt = 0; mt < 2; mt++)
#pragma unroll
                for (int nt = 0; nt < 8; nt++)
                    mma16816(acc[mt][nt], af[mt], bf[nt][0], bf[nt][1]);
        }
    }

    // Staged epilogue: fp32 acc -> fp16 smem -> coalesced 16B global stores.
    __syncthreads();
    int tg = lane >> 2, tp = lane & 3;
#pragma unroll
    for (int mt = 0; mt < 2; mt++) {
        int r0 = m0 + mt * 16 + tg;
#pragma unroll
        for (int nt = 0; nt < 8; nt++) {
            int col = n0 + nt * 8 + 2 * tp;
            __half2 hA = __floats2half2_rn(acc[mt][nt].x, acc[mt][nt].y);
            __half2 hB = __floats2half2_rn(acc[mt][nt].z, acc[mt][nt].w);
            *(__half2*)&Cs[r0 * CS_STRIDE + col] = hA;
            *(__half2*)&Cs[(r0 + 8) * CS_STRIDE + col] = hB;
        }
    }
    __syncthreads();
#pragma unroll
    for (int t = 0; t < 8; t++) {
        int i = tid + t * 256;
        int row = i >> 4, q = i & 15;
        int node = nb + row;
        if (node < N) {
            uint4 v = *(const uint4*)&Cs[row * CS_STRIDE + q * 8];
            *(uint4*)&g_h16[(size_t)node * HDIM + q * 8] = v;
        }
    }
}

// --- CSR aggregation over fp16 h: warp per node -----------------------------
__global__ void __launch_bounds__(256)
agg16_kernel(const float* __restrict__ b, int N, int mode,
             const idx_t* __restrict__ batch, int G) {
    int n = blockIdx.x * 8 + (threadIdx.x >> 5);
    if (n >= N) return;
    int lane = threadIdx.x & 31;

    float di = g_dinv[n];
    float w = di * di;
    float4 b4 = *(const float4*)&b[lane * 4];

    uint2 hs = *(const uint2*)&g_h16[(size_t)n * HDIM + lane * 4];
    float2 f0 = __half22float2(*(__half2*)&hs.x);
    float2 f1 = __half22float2(*(__half2*)&hs.y);
    float4 acc;
    acc.x = b4.x + f0.x * w; acc.y = b4.y + f0.y * w;
    acc.z = b4.z + f1.x * w; acc.w = b4.w + f1.y * w;

    int e = g_off[n];
    int end = e + g_cnt[n];
    for (; e + 1 < end; e += 2) {
        int2 c0i = g_csr[e], c1i = g_csr[e + 1];
        float n0 = __int_as_float(c0i.y), n1 = __int_as_float(c1i.y);
        uint2 u0 = *(const uint2*)&g_h16[(size_t)c0i.x * HDIM + lane * 4];
        uint2 u1 = *(const uint2*)&g_h16[(size_t)c1i.x * HDIM + lane * 4];
        float2 a0 = __half22float2(*(__half2*)&u0.x);
        float2 a1 = __half22float2(*(__half2*)&u0.y);
        float2 c0 = __half22float2(*(__half2*)&u1.x);
        float2 c1 = __half22float2(*(__half2*)&u1.y);
        acc.x += a0.x * n0 + c0.x * n1;
        acc.y += a0.y * n0 + c0.y * n1;
        acc.z += a1.x * n0 + c1.x * n1;
        acc.w += a1.y * n0 + c1.y * n1;
    }
    if (e < end) {
        int2 c0i = g_csr[e];
        float n0 = __int_as_float(c0i.y);
        uint2 u0 = *(const uint2*)&g_h16[(size_t)c0i.x * HDIM + lane * 4];
        float2 a0 = __half22float2(*(__half2*)&u0.x);
        float2 a1 = __half22float2(*(__half2*)&u0.y);
        acc.x += a0.x * n0; acc.y += a0.y * n0;
        acc.z += a1.x * n0; acc.w += a1.y * n0;
    }

    acc.x = fmaxf(acc.x, 0.f); acc.y = fmaxf(acc.y, 0.f);
    acc.z = fmaxf(acc.z, 0.f); acc.w = fmaxf(acc.w, 0.f);

    if (mode == 0) {
        __half2 h01 = __floats2half2_rn(acc.x, acc.y);
        __half2 h23 = __floats2half2_rn(acc.z, acc.w);
        *(uint2*)&g_y16[(size_t)n * HDIM + lane * 4] =
            make_uint2(*(uint32_t*)&h01, *(uint32_t*)&h23);
    } else {
        int bg = (int)__ldg(&batch[n]);
        if ((unsigned)bg < (unsigned)G) {
            float* p = &g_gsum[bg * HDIM + lane * 4];
            asm volatile("red.global.add.v4.f32 [%0], {%1,%2,%3,%4};"
                         :: "l"(p), "f"(acc.x), "f"(acc.y), "f"(acc.z), "f"(acc.w)
                         : "memory");
            if (lane == 0) atomicAdd(&g_gcnt[bg], 1.0f);
        }
    }
}

// --- Final MLP (single block) ------------------------------------------------
__global__ void mlp_kernel(const float* __restrict__ Wl1,
                           const float* __restrict__ bl1,
                           const float* __restrict__ Wl2,
                           const float* __restrict__ bl2,
                           float* __restrict__ out,
                           int G, int H2, int C) {
    __shared__ float sh[4096];
    int tid = threadIdx.x;
    for (int idx = tid; idx < G * H2; idx += blockDim.x) {
        int g = idx / H2, j = idx % H2;
        float inv = 1.0f / fmaxf(g_gcnt[g], 1.0f);
        float s = bl1[j];
        for (int k = 0; k < HDIM; k++)
            s += (g_gsum[g * HDIM + k] * inv) * Wl1[k * H2 + j];
        sh[idx] = fmaxf(s, 0.f);
    }
    __syncthreads();
    for (int idx = tid; idx < G * C; idx += blockDim.x) {
        int g = idx / C, c = idx % C;
        float s = bl2[c];
        for (int j = 0; j < H2; j++)
            s += sh[g * H2 + j] * Wl2[j * C + c];
        out[idx] = s;
    }
}

// ---------------------------------------------------------------------------
extern "C" void kernel_launch(void* const* d_in, const int* in_sizes, int n_in,
                              void* d_out, int out_size) {
    const float* pos  = (const float*)d_in[0];
    const idx_t* ei   = (const idx_t*)d_in[1];
    const idx_t* batch= (const idx_t*)d_in[2];
    const float* W1   = (const float*)d_in[3];
    const float* b1   = (const float*)d_in[4];
    const float* W2   = (const float*)d_in[5];
    const float* b2   = (const float*)d_in[6];
    const float* W3   = (const float*)d_in[7];
    const float* b3   = (const float*)d_in[8];
    const float* Wl1  = (const float*)d_in[9];
    const float* bl1  = (const float*)d_in[10];
    const float* Wl2  = (const float*)d_in[11];
    const float* bl2  = (const float*)d_in[12];
    float* out = (float*)d_out;

    int H  = in_sizes[4];              // 128
    int D  = in_sizes[3] / H;          // 3
    int N  = in_sizes[0] / D;          // 50000
    int E  = in_sizes[1] / 2;          // 800000
    int H2 = in_sizes[10];             // 64
    int C  = in_sizes[12];             // 10
    int G  = out_size / C;             // 64

    int initN = N > G * H ? N : G * H;
    setup_kernel<<<(initN + 255) / 256, 256>>>(N, G * H, G);
    wconv_kernel<<<(HDIM * HDIM + 255) / 256, 256>>>(W2, W3);
    hist_kernel<<<(E + 255) / 256, 256>>>(ei, E, N);
    scan_kernel<<<(N + SCAN_CHUNK - 1) / SCAN_CHUNK, 1024>>>(N);
    edge_fill<<<(E + 255) / 256, 256>>>(ei, E, N);

    // Layer 1 (fused: pos-space aggregation + dense + relu)
    layer1_kernel<<<(N + 7) / 8, 256>>>(pos, W1, b1, N);

    // Layer 2
    dense_mma_kernel<<<(N + 127) / 128, 256>>>(2, N);
    agg16_kernel<<<(N + 7) / 8, 256>>>(b2, N, 0, batch, G);

    // Layer 3 (aggregation fused with mean-pool)
    dense_mma_kernel<<<(N + 127) / 128, 256>>>(3, N);
    agg16_kernel<<<(N + 7) / 8, 256>>>(b3, N, 1, batch, G);

    mlp_kernel<<<1, 256>>>(Wl1, bl1, Wl2, bl2, out, G, H2, C);
}

// round 9
// speedup vs baseline: 2.8428x; 1.2940x over previous
#include <cuda_runtime.h>
#include <cuda_fp16.h>
#include <cstdint>

// ---------------------------------------------------------------------------
// GCN 3-layer + mean-pool + MLP for GB300 (sm_103a) — Round 9
//  * scan reshaped 13x1024 -> 49x256 blocks (latency-bound; 4x SM coverage)
//  * MLP block-per-graph (kills 16 serial 128-FMA chains per thread)
//  * setup+wconv merged (one fewer launch)
//  * agg16 4-edge unroll (MLP_eff 2 -> 4 on the gather path)
//  * rank-from-histogram CSR, packed int2 payload, fp16 hidden, HMMA dense
// Shape: N=50000, E=800000, D=3, H=128, G=64, H2=64, C=10
// ---------------------------------------------------------------------------

#define HDIM 128
#define MAXN 50176
#define MAXE 850000
#define MAXG 256

typedef int idx_t;

// Scratch
__device__ __half g_y16[MAXN * HDIM];   // GEMM input / agg output (zero past N)
__device__ __half g_h16[MAXN * HDIM];   // GEMM output / gather source
__device__ __half g_w2h[HDIM * HDIM];   // W2 in fp16
__device__ __half g_w3h[HDIM * HDIM];   // W3 in fp16
__device__ float g_dinv[MAXN];
__device__ int   g_cnt[MAXN];
__device__ int   g_rank[MAXE];          // edge rank within its dst
__device__ int   g_off[MAXN];
__device__ int2  g_csr[MAXE];           // {src, nrm as bits}
__device__ float g_gsum[MAXG * HDIM];
__device__ float g_gcnt[MAXG];
// decoupled-lookback state: hi 32 = flag (0/1/2), lo 32 = value; single 8B op.
__device__ unsigned long long g_state[64];

// --------------------------- PTX helpers (baseline ISA only) ----------------
__device__ __forceinline__ uint32_t smem_u32(const void* p) {
    uint32_t a;
    asm("{ .reg .u64 t; cvta.to.shared.u64 t, %1; cvt.u32.u64 %0, t; }"
        : "=r"(a) : "l"(p));
    return a;
}

__device__ __forceinline__ void ldsm_x4(uint32_t& r0, uint32_t& r1,
                                        uint32_t& r2, uint32_t& r3, uint32_t a) {
    asm volatile("ldmatrix.sync.aligned.m8n8.x4.shared.b16 {%0,%1,%2,%3}, [%4];"
                 : "=r"(r0), "=r"(r1), "=r"(r2), "=r"(r3) : "r"(a));
}

__device__ __forceinline__ void ldsm_x4_t(uint32_t& r0, uint32_t& r1,
                                          uint32_t& r2, uint32_t& r3, uint32_t a) {
    asm volatile("ldmatrix.sync.aligned.m8n8.x4.trans.shared.b16 {%0,%1,%2,%3}, [%4];"
                 : "=r"(r0), "=r"(r1), "=r"(r2), "=r"(r3) : "r"(a));
}

__device__ __forceinline__ void mma16816(float4& c, const uint32_t* a,
                                         uint32_t b0, uint32_t b1) {
    asm volatile("mma.sync.aligned.m16n8k16.row.col.f32.f16.f16.f32 "
                 "{%0,%1,%2,%3}, {%4,%5,%6,%7}, {%8,%9}, {%0,%1,%2,%3};"
                 : "+f"(c.x), "+f"(c.y), "+f"(c.z), "+f"(c.w)
                 : "r"(a[0]), "r"(a[1]), "r"(a[2]), "r"(a[3]),
                   "r"(b0), "r"(b1));
}

__device__ __forceinline__ void state_store(int b, unsigned long long v) {
    asm volatile("st.volatile.global.u64 [%0], %1;"
                 :: "l"(&g_state[b]), "l"(v) : "memory");
}

__device__ __forceinline__ unsigned long long state_load(int b) {
    unsigned long long v;
    asm volatile("ld.volatile.global.u64 %0, [%1];"
                 : "=l"(v) : "l"(&g_state[b]) : "memory");
    return v;
}

// ---------------------------------------------------------------------------
// setup + W2/W3 fp16 conversion (merged)
__global__ void setup_kernel(const float* __restrict__ W2,
                             const float* __restrict__ W3,
                             int N, int GH, int G) {
    int i = blockIdx.x * blockDim.x + threadIdx.x;
    if (i < N) g_cnt[i] = 0;
    if (i < GH) g_gsum[i] = 0.0f;
    if (i < G) g_gcnt[i] = 0.0f;
    if (i < 64) g_state[i] = 0ull;
    if (i < HDIM * HDIM) {
        g_w2h[i] = __float2half(W2[i]);
        g_w3h[i] = __float2half(W3[i]);
    }
}

// Histogram + edge rank (atomicAdd's return value = unique slot within dst)
__global__ void hist_kernel(const idx_t* __restrict__ ei, int E, int N) {
    int e = blockIdx.x * blockDim.x + threadIdx.x;
    if (e >= E) return;
    int d = (int)ei[(long long)E + e];
    int r = 0;
    if ((unsigned)d < (unsigned)N) r = atomicAdd(&g_cnt[d], 1);
    g_rank[e] = r;
}

// --- single-pass decoupled-lookback exclusive scan of g_cnt -> g_off --------
// 256 threads x 4 elems = 1024 chunk -> 49 blocks (latency coverage).
#define SCAN_T 4
#define SCAN_THREADS 256
#define SCAN_CHUNK (SCAN_THREADS * SCAN_T)

__global__ void __launch_bounds__(SCAN_THREADS)
scan_kernel(int N) {
    __shared__ int warp_sums[8];
    __shared__ int s_base;
    int b = blockIdx.x, t = threadIdx.x;
    int base = b * SCAN_CHUNK + t * SCAN_T;

    int v[SCAN_T];
    int sum = 0;
#pragma unroll
    for (int i = 0; i < SCAN_T; i++) {
        int idx = base + i;
        v[i] = (idx < N) ? g_cnt[idx] : 0;
        sum += v[i];
    }
    int lane = t & 31, wid = t >> 5;
    int x = sum;
#pragma unroll
    for (int o = 1; o < 32; o <<= 1) {
        int y = __shfl_up_sync(0xFFFFFFFFu, x, o);
        if (lane >= o) x += y;
    }
    if (lane == 31) warp_sums[wid] = x;
    __syncthreads();
    if (wid == 0 && lane < 8) {
        int y = warp_sums[lane];
#pragma unroll
        for (int o = 1; o < 8; o <<= 1) {
            int z = __shfl_up_sync(0xFFu, y, o);
            if (lane >= o) y += z;
        }
        warp_sums[lane] = y;
    }
    __syncthreads();
    int thread_excl = x - sum + (wid > 0 ? warp_sums[wid - 1] : 0);
    int block_total = warp_sums[7];

    if (t == 0) {
        if (b == 0) {
            s_base = 0;
            state_store(0, (2ull << 32) | (unsigned)block_total);
        } else {
            state_store(b, (1ull << 32) | (unsigned)block_total);
            int excl = 0;
            for (int j = b - 1; j >= 0;) {
                unsigned long long st;
                do { st = state_load(j); } while ((st >> 32) == 0);
                excl += (int)(unsigned)st;
                if ((st >> 32) == 2ull) break;
                j--;
            }
            s_base = excl;
            state_store(b, (2ull << 32) | (unsigned)(excl + block_total));
        }
    }
    __syncthreads();

    int off = s_base + thread_excl;
#pragma unroll
    for (int i = 0; i < SCAN_T; i++) {
        int idx = base + i;
        if (idx < N) {
            g_off[idx] = off;
            off += v[i];
            g_dinv[idx] = rsqrtf((float)(v[i] + 1));
        }
    }
}

// CSR fill: slot = off[d] + precomputed rank; one 8B scattered store per edge.
__global__ void edge_fill(const idx_t* __restrict__ ei, int E, int N) {
    int e = blockIdx.x * blockDim.x + threadIdx.x;
    if (e >= E) return;
    int s = (int)ei[e];
    int d = (int)ei[(long long)E + e];
    if ((unsigned)s >= (unsigned)N || (unsigned)d >= (unsigned)N) return;
    int p = g_off[d] + g_rank[e];
    if (p < MAXE) {            // belt-and-braces: degrade to wrong-answer, not UB
        float nr = g_dinv[s] * g_dinv[d];
        g_csr[p] = make_int2(s, __float_as_int(nr));
    }
}

// --- Fused layer 1: pos-space aggregation + dense + relu -> fp16 ------------
__global__ void __launch_bounds__(256)
layer1_kernel(const float* __restrict__ pos,
              const float* __restrict__ W1,
              const float* __restrict__ b1, int N) {
    int n = blockIdx.x * 8 + (threadIdx.x >> 5);
    if (n >= N) return;
    int lane = threadIdx.x & 31;

    float a0 = 0.f, a1 = 0.f, a2 = 0.f;
    int e0 = g_off[n], end = e0 + g_cnt[n];
    for (int e = e0 + lane; e < end; e += 32) {
        int2 c = g_csr[e];
        int s = c.x;
        float nr = __int_as_float(c.y);
        a0 += pos[s * 3 + 0] * nr;
        a1 += pos[s * 3 + 1] * nr;
        a2 += pos[s * 3 + 2] * nr;
    }
#pragma unroll
    for (int o = 16; o > 0; o >>= 1) {
        a0 += __shfl_down_sync(0xFFFFFFFFu, a0, o);
        a1 += __shfl_down_sync(0xFFFFFFFFu, a1, o);
        a2 += __shfl_down_sync(0xFFFFFFFFu, a2, o);
    }
    float di = g_dinv[n];
    float w = di * di;
    float x0 = __shfl_sync(0xFFFFFFFFu, a0, 0) + pos[n * 3 + 0] * w;
    float x1 = __shfl_sync(0xFFFFFFFFu, a1, 0) + pos[n * 3 + 1] * w;
    float x2 = __shfl_sync(0xFFFFFFFFu, a2, 0) + pos[n * 3 + 2] * w;

    int q = lane;
    float4 w0 = *(const float4*)&W1[0 * HDIM + q * 4];
    float4 w1 = *(const float4*)&W1[1 * HDIM + q * 4];
    float4 w2 = *(const float4*)&W1[2 * HDIM + q * 4];
    float4 b4 = *(const float4*)&b1[q * 4];
    float4 a;
    a.x = fmaxf(b4.x + x0 * w0.x + x1 * w1.x + x2 * w2.x, 0.f);
    a.y = fmaxf(b4.y + x0 * w0.y + x1 * w1.y + x2 * w2.y, 0.f);
    a.z = fmaxf(b4.z + x0 * w0.z + x1 * w1.z + x2 * w2.z, 0.f);
    a.w = fmaxf(b4.w + x0 * w0.w + x1 * w1.w + x2 * w2.w, 0.f);
    __half2 h01 = __floats2half2_rn(a.x, a.y);
    __half2 h23 = __floats2half2_rn(a.z, a.w);
    *(uint2*)&g_y16[(size_t)n * HDIM + q * 4] =
        make_uint2(*(uint32_t*)&h01, *(uint32_t*)&h23);
}

// --- Dense layers 2/3 via HMMA: h16 = y16 @ Wh (128x128x128 per block) ------
#define AS_STRIDE 72    // halves per A row (64 + 8 pad)
#define BS_STRIDE 136   // halves per B row (128 + 8 pad)
#define CS_STRIDE 136   // halves per C row for staged epilogue

__global__ void __launch_bounds__(256)
dense_mma_kernel(int layer, int N) {
    const __half* __restrict__ Wh = (layer == 2) ? g_w2h : g_w3h;

    __shared__ __align__(16) char smraw[(128 * AS_STRIDE + 64 * BS_STRIDE) * 2];
    __half* As = (__half*)smraw;                     // 128 x 72
    __half* Bs = As + 128 * AS_STRIDE;               // 64 x 136
    __half* Cs = (__half*)smraw;                     // 128 x 136 (reuse)

    int tid = threadIdx.x;
    int wid = tid >> 5;
    int lane = tid & 31;
    int nb = blockIdx.x * 128;

    int m0 = (wid & 3) * 32;
    int n0 = (wid >> 2) * 64;

    float4 acc[2][8];
#pragma unroll
    for (int i = 0; i < 2; i++)
#pragma unroll
        for (int j = 0; j < 8; j++) acc[i][j] = make_float4(0.f, 0.f, 0.f, 0.f);

    for (int c = 0; c < 2; c++) {
        __syncthreads();
        // A chunk: 128 rows x 64 halves (8 uint4/row)
#pragma unroll
        for (int t = 0; t < 4; t++) {
            int i = tid + t * 256;
            int row = i >> 3, q = i & 7;
            uint4 v = *(const uint4*)&g_y16[(size_t)(nb + row) * HDIM + c * 64 + q * 8];
            *(uint4*)&As[row * AS_STRIDE + q * 8] = v;
        }
        // B chunk (fp16): rows c*64..+63, 128 halves/row = 16 uint4/row
#pragma unroll
        for (int t = 0; t < 4; t++) {
            int i = tid + t * 256;
            int row = i >> 4, q = i & 15;
            uint4 v = *(const uint4*)&Wh[(size_t)(c * 64 + row) * HDIM + q * 8];
            *(uint4*)&Bs[row * BS_STRIDE + q * 8] = v;
        }
        __syncthreads();

#pragma unroll
        for (int kk = 0; kk < 4; kk++) {
            int k16 = kk * 16;
            uint32_t af[2][4];
#pragma unroll
            for (int mt = 0; mt < 2; mt++) {
                uint32_t a = smem_u32(
                    &As[(m0 + mt * 16 + (lane & 15)) * AS_STRIDE + k16 + (lane >> 4) * 8]);
                ldsm_x4(af[mt][0], af[mt][1], af[mt][2], af[mt][3], a);
            }
            uint32_t bf[8][2];
#pragma unroll
            for (int nt2 = 0; nt2 < 4; nt2++) {
                uint32_t a = smem_u32(
                    &Bs[(k16 + (lane & 15)) * BS_STRIDE + n0 + nt2 * 16 + (lane >> 4) * 8]);
                uint32_t r0, r1, r2, r3;
                ldsm_x4_t(r0, r1, r2, r3, a);
                bf[nt2 * 2 + 0][0] = r0; bf[nt2 * 2 + 0][1] = r1;
                bf[nt2 * 2 + 1][0] = r2; bf[nt2 * 2 + 1][1] = r3;
            }
#pragma unroll
            for (int mt = 0; mt < 2; mt++)
#pragma unroll
                for (int nt = 0; nt < 8; nt++)
                    mma16816(acc[mt][nt], af[mt], bf[nt][0], bf[nt][1]);
        }
    }

    // Staged epilogue: fp32 acc -> fp16 smem -> coalesced 16B global stores.
    __syncthreads();
    int tg = lane >> 2, tp = lane & 3;
#pragma unroll
    for (int mt = 0; mt < 2; mt++) {
        int r0 = m0 + mt * 16 + tg;
#pragma unroll
        for (int nt = 0; nt < 8; nt++) {
            int col = n0 + nt * 8 + 2 * tp;
            __half2 hA = __floats2half2_rn(acc[mt][nt].x, acc[mt][nt].y);
            __half2 hB = __floats2half2_rn(acc[mt][nt].z, acc[mt][nt].w);
            *(__half2*)&Cs[r0 * CS_STRIDE + col] = hA;
            *(__half2*)&Cs[(r0 + 8) * CS_STRIDE + col] = hB;
        }
    }
    __syncthreads();
#pragma unroll
    for (int t = 0; t < 8; t++) {
        int i = tid + t * 256;
        int row = i >> 4, q = i & 15;
        int node = nb + row;
        if (node < N) {
            uint4 v = *(const uint4*)&Cs[row * CS_STRIDE + q * 8];
            *(uint4*)&g_h16[(size_t)node * HDIM + q * 8] = v;
        }
    }
}

// --- CSR aggregation over fp16 h: warp per node, 4-edge unrolled gather -----
__global__ void __launch_bounds__(256)
agg16_kernel(const float* __restrict__ b, int N, int mode,
             const idx_t* __restrict__ batch, int G) {
    int n = blockIdx.x * 8 + (threadIdx.x >> 5);
    if (n >= N) return;
    int lane = threadIdx.x & 31;

    float di = g_dinv[n];
    float w = di * di;
    float4 b4 = *(const float4*)&b[lane * 4];

    uint2 hs = *(const uint2*)&g_h16[(size_t)n * HDIM + lane * 4];
    float2 f0 = __half22float2(*(__half2*)&hs.x);
    float2 f1 = __half22float2(*(__half2*)&hs.y);
    float4 acc;
    acc.x = b4.x + f0.x * w; acc.y = b4.y + f0.y * w;
    acc.z = b4.z + f1.x * w; acc.w = b4.w + f1.y * w;

    int e = g_off[n];
    int end = e + g_cnt[n];
    // 4-edge unrolled main loop: 4 independent CSR loads, then 4 independent
    // 8B gathers in flight before any FMA consumes them.
    for (; e + 3 < end; e += 4) {
        int2 ci0 = g_csr[e],     ci1 = g_csr[e + 1];
        int2 ci2 = g_csr[e + 2], ci3 = g_csr[e + 3];
        uint2 u0 = *(const uint2*)&g_h16[(size_t)ci0.x * HDIM + lane * 4];
        uint2 u1 = *(const uint2*)&g_h16[(size_t)ci1.x * HDIM + lane * 4];
        uint2 u2 = *(const uint2*)&g_h16[(size_t)ci2.x * HDIM + lane * 4];
        uint2 u3 = *(const uint2*)&g_h16[(size_t)ci3.x * HDIM + lane * 4];
        float n0 = __int_as_float(ci0.y), n1 = __int_as_float(ci1.y);
        float n2 = __int_as_float(ci2.y), n3 = __int_as_float(ci3.y);
        float2 p0 = __half22float2(*(__half2*)&u0.x);
        float2 q0 = __half22float2(*(__half2*)&u0.y);
        float2 p1 = __half22float2(*(__half2*)&u1.x);
        float2 q1 = __half22float2(*(__half2*)&u1.y);
        float2 p2 = __half22float2(*(__half2*)&u2.x);
        float2 q2 = __half22float2(*(__half2*)&u2.y);
        float2 p3 = __half22float2(*(__half2*)&u3.x);
        float2 q3 = __half22float2(*(__half2*)&u3.y);
        acc.x += p0.x * n0 + p1.x * n1 + p2.x * n2 + p3.x * n3;
        acc.y += p0.y * n0 + p1.y * n1 + p2.y * n2 + p3.y * n3;
        acc.z += q0.x * n0 + q1.x * n1 + q2.x * n2 + q3.x * n3;
        acc.w += q0.y * n0 + q1.y * n1 + q2.y * n2 + q3.y * n3;
    }
    for (; e < end; e++) {
        int2 ci = g_csr[e];
        float nr = __int_as_float(ci.y);
        uint2 u0 = *(const uint2*)&g_h16[(size_t)ci.x * HDIM + lane * 4];
        float2 p0 = __half22float2(*(__half2*)&u0.x);
        float2 q0 = __half22float2(*(__half2*)&u0.y);
        acc.x += p0.x * nr; acc.y += p0.y * nr;
        acc.z += q0.x * nr; acc.w += q0.y * nr;
    }

    acc.x = fmaxf(acc.x, 0.f); acc.y = fmaxf(acc.y, 0.f);
    acc.z = fmaxf(acc.z, 0.f); acc.w = fmaxf(acc.w, 0.f);

    if (mode == 0) {
        __half2 h01 = __floats2half2_rn(acc.x, acc.y);
        __half2 h23 = __floats2half2_rn(acc.z, acc.w);
        *(uint2*)&g_y16[(size_t)n * HDIM + lane * 4] =
            make_uint2(*(uint32_t*)&h01, *(uint32_t*)&h23);
    } else {
        int bg = (int)__ldg(&batch[n]);
        if ((unsigned)bg < (unsigned)G) {
            float* p = &g_gsum[bg * HDIM + lane * 4];
            asm volatile("red.global.add.v4.f32 [%0], {%1,%2,%3,%4};"
                         :: "l"(p), "f"(acc.x), "f"(acc.y), "f"(acc.z), "f"(acc.w)
                         : "memory");
            if (lane == 0) atomicAdd(&g_gcnt[bg], 1.0f);
        }
    }
}

// --- Final MLP: one block per graph ------------------------------------------
__global__ void __launch_bounds__(128)
mlp_kernel(const float* __restrict__ Wl1,
           const float* __restrict__ bl1,
           const float* __restrict__ Wl2,
           const float* __restrict__ bl2,
           float* __restrict__ out,
           int H2, int C) {
    __shared__ float xs[HDIM];   // pooled mean for this graph
    __shared__ float h1[64];     // hidden layer (H2 <= 64)
    int g = blockIdx.x;
    int tid = threadIdx.x;

    float inv = 1.0f / fmaxf(g_gcnt[g], 1.0f);
    if (tid < HDIM) xs[tid] = g_gsum[g * HDIM + tid] * inv;
    __syncthreads();

    if (tid < H2) {
        float s = bl1[tid];
        for (int k = 0; k < HDIM; k++)
            s += xs[k] * Wl1[k * H2 + tid];
        h1[tid] = fmaxf(s, 0.f);
    }
    __syncthreads();

    if (tid < C) {
        float s = bl2[tid];
        for (int j = 0; j < H2; j++)
            s += h1[j] * Wl2[j * C + tid];
        out[g * C + tid] = s;
    }
}

// ---------------------------------------------------------------------------
extern "C" void kernel_launch(void* const* d_in, const int* in_sizes, int n_in,
                              void* d_out, int out_size) {
    const float* pos  = (const float*)d_in[0];
    const idx_t* ei   = (const idx_t*)d_in[1];
    const idx_t* batch= (const idx_t*)d_in[2];
    const float* W1   = (const float*)d_in[3];
    const float* b1   = (const float*)d_in[4];
    const float* W2   = (const float*)d_in[5];
    const float* b2   = (const float*)d_in[6];
    const float* W3   = (const float*)d_in[7];
    const float* b3   = (const float*)d_in[8];
    const float* Wl1  = (const float*)d_in[9];
    const float* bl1  = (const float*)d_in[10];
    const float* Wl2  = (const float*)d_in[11];
    const float* bl2  = (const float*)d_in[12];
    float* out = (float*)d_out;

    int H  = in_sizes[4];              // 128
    int D  = in_sizes[3] / H;          // 3
    int N  = in_sizes[0] / D;          // 50000
    int E  = in_sizes[1] / 2;          // 800000
    int H2 = in_sizes[10];             // 64
    int C  = in_sizes[12];             // 10
    int G  = out_size / C;             // 64

    int initN = N > G * H ? N : G * H;
    setup_kernel<<<(initN + 255) / 256, 256>>>(W2, W3, N, G * H, G);
    hist_kernel<<<(E + 255) / 256, 256>>>(ei, E, N);
    scan_kernel<<<(N + SCAN_CHUNK - 1) / SCAN_CHUNK, SCAN_THREADS>>>(N);
    edge_fill<<<(E + 255) / 256, 256>>>(ei, E, N);

    // Layer 1 (fused: pos-space aggregation + dense + relu)
    layer1_kernel<<<(N + 7) / 8, 256>>>(pos, W1, b1, N);

    // Layer 2
    dense_mma_kernel<<<(N + 127) / 128, 256>>>(2, N);
    agg16_kernel<<<(N + 7) / 8, 256>>>(b2, N, 0, batch, G);

    // Layer 3 (aggregation fused with mean-pool)
    dense_mma_kernel<<<(N + 127) / 128, 256>>>(3, N);
    agg16_kernel<<<(N + 7) / 8, 256>>>(b3, N, 1, batch, G);

    mlp_kernel<<<G, 128>>>(Wl1, bl1, Wl2, bl2, out, H2, C);
}

// round 10
// speedup vs baseline: 3.0510x; 1.0732x over previous
#include <cuda_runtime.h>
#include <cuda_fp16.h>
#include <cstdint>

// ---------------------------------------------------------------------------
// GCN 3-layer + mean-pool + MLP for GB300 (sm_103a) — Round 10
//  * factored normalization: dense epilogue stores h' = h*dinv[row];
//    agg computes relu(b + dinv[d]*(h'[d] + sum h'[src])) -> CSR payload is
//    src-only (4B), edge_fill loses nrm computation + dinv gathers
//  * pos' = pos*dinv precomputed in scan (float4) -> layer1 gather is 1x16B
//  * scan 49x256 lookback, MLP block-per-graph, 4-edge unrolled agg,
//    rank-from-histogram CSR, fp16 hidden, HMMA dense
// Shape: N=50000, E=800000, D=3, H=128, G=64, H2=64, C=10
// ---------------------------------------------------------------------------

#define HDIM 128
#define MAXN 50176
#define MAXE 850000
#define MAXG 256

typedef int idx_t;

// Scratch
__device__ __half g_y16[MAXN * HDIM];   // GEMM input / agg output (zero past N)
__device__ __half g_h16[MAXN * HDIM];   // GEMM output, pre-scaled by dinv[row]
__device__ __half g_w2h[HDIM * HDIM];   // W2 in fp16
__device__ __half g_w3h[HDIM * HDIM];   // W3 in fp16
__device__ float4 g_pos4[MAXN];         // pos * dinv (xyz), w unused
__device__ float g_dinv[MAXN];
__device__ int   g_cnt[MAXN];
__device__ int   g_rank[MAXE];          // edge rank within its dst
__device__ int   g_off[MAXN];
__device__ int   g_csr_src[MAXE];       // src-only CSR payload
__device__ float g_gsum[MAXG * HDIM];
__device__ float g_gcnt[MAXG];
// decoupled-lookback state: hi 32 = flag (0/1/2), lo 32 = value; single 8B op.
__device__ unsigned long long g_state[64];

// --------------------------- PTX helpers (baseline ISA only) ----------------
__device__ __forceinline__ uint32_t smem_u32(const void* p) {
    uint32_t a;
    asm("{ .reg .u64 t; cvta.to.shared.u64 t, %1; cvt.u32.u64 %0, t; }"
        : "=r"(a) : "l"(p));
    return a;
}

__device__ __forceinline__ void ldsm_x4(uint32_t& r0, uint32_t& r1,
                                        uint32_t& r2, uint32_t& r3, uint32_t a) {
    asm volatile("ldmatrix.sync.aligned.m8n8.x4.shared.b16 {%0,%1,%2,%3}, [%4];"
                 : "=r"(r0), "=r"(r1), "=r"(r2), "=r"(r3) : "r"(a));
}

__device__ __forceinline__ void ldsm_x4_t(uint32_t& r0, uint32_t& r1,
                                          uint32_t& r2, uint32_t& r3, uint32_t a) {
    asm volatile("ldmatrix.sync.aligned.m8n8.x4.trans.shared.b16 {%0,%1,%2,%3}, [%4];"
                 : "=r"(r0), "=r"(r1), "=r"(r2), "=r"(r3) : "r"(a));
}

__device__ __forceinline__ void mma16816(float4& c, const uint32_t* a,
                                         uint32_t b0, uint32_t b1) {
    asm volatile("mma.sync.aligned.m16n8k16.row.col.f32.f16.f16.f32 "
                 "{%0,%1,%2,%3}, {%4,%5,%6,%7}, {%8,%9}, {%0,%1,%2,%3};"
                 : "+f"(c.x), "+f"(c.y), "+f"(c.z), "+f"(c.w)
                 : "r"(a[0]), "r"(a[1]), "r"(a[2]), "r"(a[3]),
                   "r"(b0), "r"(b1));
}

__device__ __forceinline__ void state_store(int b, unsigned long long v) {
    asm volatile("st.volatile.global.u64 [%0], %1;"
                 :: "l"(&g_state[b]), "l"(v) : "memory");
}

__device__ __forceinline__ unsigned long long state_load(int b) {
    unsigned long long v;
    asm volatile("ld.volatile.global.u64 %0, [%1];"
                 : "=l"(v) : "l"(&g_state[b]) : "memory");
    return v;
}

// ---------------------------------------------------------------------------
// setup + W2/W3 fp16 conversion (merged)
__global__ void setup_kernel(const float* __restrict__ W2,
                             const float* __restrict__ W3,
                             int N, int GH, int G) {
    int i = blockIdx.x * blockDim.x + threadIdx.x;
    if (i < N) g_cnt[i] = 0;
    if (i < GH) g_gsum[i] = 0.0f;
    if (i < G) g_gcnt[i] = 0.0f;
    if (i < 64) g_state[i] = 0ull;
    if (i < HDIM * HDIM) {
        g_w2h[i] = __float2half(W2[i]);
        g_w3h[i] = __float2half(W3[i]);
    }
}

// Histogram + edge rank (atomicAdd's return value = unique slot within dst)
__global__ void hist_kernel(const idx_t* __restrict__ ei, int E, int N) {
    int e = blockIdx.x * blockDim.x + threadIdx.x;
    if (e >= E) return;
    int d = (int)ei[(long long)E + e];
    int r = 0;
    if ((unsigned)d < (unsigned)N) r = atomicAdd(&g_cnt[d], 1);
    g_rank[e] = r;
}

// --- single-pass decoupled-lookback scan; also emits dinv and pos*dinv ------
#define SCAN_T 4
#define SCAN_THREADS 256
#define SCAN_CHUNK (SCAN_THREADS * SCAN_T)

__global__ void __launch_bounds__(SCAN_THREADS)
scan_kernel(const float* __restrict__ pos, int N) {
    __shared__ int warp_sums[8];
    __shared__ int s_base;
    int b = blockIdx.x, t = threadIdx.x;
    int base = b * SCAN_CHUNK + t * SCAN_T;

    int v[SCAN_T];
    int sum = 0;
#pragma unroll
    for (int i = 0; i < SCAN_T; i++) {
        int idx = base + i;
        v[i] = (idx < N) ? g_cnt[idx] : 0;
        sum += v[i];
    }
    int lane = t & 31, wid = t >> 5;
    int x = sum;
#pragma unroll
    for (int o = 1; o < 32; o <<= 1) {
        int y = __shfl_up_sync(0xFFFFFFFFu, x, o);
        if (lane >= o) x += y;
    }
    if (lane == 31) warp_sums[wid] = x;
    __syncthreads();
    if (wid == 0 && lane < 8) {
        int y = warp_sums[lane];
#pragma unroll
        for (int o = 1; o < 8; o <<= 1) {
            int z = __shfl_up_sync(0xFFu, y, o);
            if (lane >= o) y += z;
        }
        warp_sums[lane] = y;
    }
    __syncthreads();
    int thread_excl = x - sum + (wid > 0 ? warp_sums[wid - 1] : 0);
    int block_total = warp_sums[7];

    if (t == 0) {
        if (b == 0) {
            s_base = 0;
            state_store(0, (2ull << 32) | (unsigned)block_total);
        } else {
            state_store(b, (1ull << 32) | (unsigned)block_total);
            int excl = 0;
            for (int j = b - 1; j >= 0;) {
                unsigned long long st;
                do { st = state_load(j); } while ((st >> 32) == 0);
                excl += (int)(unsigned)st;
                if ((st >> 32) == 2ull) break;
                j--;
            }
            s_base = excl;
            state_store(b, (2ull << 32) | (unsigned)(excl + block_total));
        }
    }
    __syncthreads();

    int off = s_base + thread_excl;
#pragma unroll
    for (int i = 0; i < SCAN_T; i++) {
        int idx = base + i;
        if (idx < N) {
            g_off[idx] = off;
            off += v[i];
            float di = rsqrtf((float)(v[i] + 1));
            g_dinv[idx] = di;
            g_pos4[idx] = make_float4(pos[idx * 3 + 0] * di,
                                      pos[idx * 3 + 1] * di,
                                      pos[idx * 3 + 2] * di, 0.f);
        }
    }
}

// CSR fill: slot = off[d] + rank; one 4B scattered store, no dinv gathers.
__global__ void edge_fill(const idx_t* __restrict__ ei, int E, int N) {
    int e = blockIdx.x * blockDim.x + threadIdx.x;
    if (e >= E) return;
    int s = (int)ei[e];
    int d = (int)ei[(long long)E + e];
    if ((unsigned)s >= (unsigned)N || (unsigned)d >= (unsigned)N) return;
    int p = g_off[d] + g_rank[e];
    if (p < MAXE) g_csr_src[p] = s;
}

// --- Fused layer 1: pos'-space aggregation + dense + relu -> fp16 -----------
// x[d] = dinv[d] * (pos'[d] + sum pos'[src]);  y1 = relu(b1 + W1^T x)
__global__ void __launch_bounds__(256)
layer1_kernel(const float* __restrict__ W1,
              const float* __restrict__ b1, int N) {
    int n = blockIdx.x * 8 + (threadIdx.x >> 5);
    if (n >= N) return;
    int lane = threadIdx.x & 31;

    float a0 = 0.f, a1 = 0.f, a2 = 0.f;
    int e0 = g_off[n], end = e0 + g_cnt[n];
    for (int e = e0 + lane; e < end; e += 32) {
        float4 p = g_pos4[g_csr_src[e]];
        a0 += p.x; a1 += p.y; a2 += p.z;
    }
#pragma unroll
    for (int o = 16; o > 0; o >>= 1) {
        a0 += __shfl_down_sync(0xFFFFFFFFu, a0, o);
        a1 += __shfl_down_sync(0xFFFFFFFFu, a1, o);
        a2 += __shfl_down_sync(0xFFFFFFFFu, a2, o);
    }
    float di = g_dinv[n];
    float4 ps = g_pos4[n];
    float x0 = (__shfl_sync(0xFFFFFFFFu, a0, 0) + ps.x) * di;
    float x1 = (__shfl_sync(0xFFFFFFFFu, a1, 0) + ps.y) * di;
    float x2 = (__shfl_sync(0xFFFFFFFFu, a2, 0) + ps.z) * di;

    int q = lane;
    float4 w0 = *(const float4*)&W1[0 * HDIM + q * 4];
    float4 w1 = *(const float4*)&W1[1 * HDIM + q * 4];
    float4 w2 = *(const float4*)&W1[2 * HDIM + q * 4];
    float4 b4 = *(const float4*)&b1[q * 4];
    float4 a;
    a.x = fmaxf(b4.x + x0 * w0.x + x1 * w1.x + x2 * w2.x, 0.f);
    a.y = fmaxf(b4.y + x0 * w0.y + x1 * w1.y + x2 * w2.y, 0.f);
    a.z = fmaxf(b4.z + x0 * w0.z + x1 * w1.z + x2 * w2.z, 0.f);
    a.w = fmaxf(b4.w + x0 * w0.w + x1 * w1.w + x2 * w2.w, 0.f);
    __half2 h01 = __floats2half2_rn(a.x, a.y);
    __half2 h23 = __floats2half2_rn(a.z, a.w);
    *(uint2*)&g_y16[(size_t)n * HDIM + q * 4] =
        make_uint2(*(uint32_t*)&h01, *(uint32_t*)&h23);
}

// --- Dense layers 2/3 via HMMA; epilogue stores h' = h*dinv[row] ------------
#define AS_STRIDE 72    // halves per A row (64 + 8 pad)
#define BS_STRIDE 136   // halves per B row (128 + 8 pad)
#define CS_STRIDE 136   // halves per C row for staged epilogue

__global__ void __launch_bounds__(256)
dense_mma_kernel(int layer, int N) {
    const __half* __restrict__ Wh = (layer == 2) ? g_w2h : g_w3h;

    __shared__ __align__(16) char smraw[(128 * AS_STRIDE + 64 * BS_STRIDE) * 2];
    __half* As = (__half*)smraw;                     // 128 x 72
    __half* Bs = As + 128 * AS_STRIDE;               // 64 x 136
    __half* Cs = (__half*)smraw;                     // 128 x 136 (reuse)

    int tid = threadIdx.x;
    int wid = tid >> 5;
    int lane = tid & 31;
    int nb = blockIdx.x * 128;

    int m0 = (wid & 3) * 32;
    int n0 = (wid >> 2) * 64;

    float4 acc[2][8];
#pragma unroll
    for (int i = 0; i < 2; i++)
#pragma unroll
        for (int j = 0; j < 8; j++) acc[i][j] = make_float4(0.f, 0.f, 0.f, 0.f);

    for (int c = 0; c < 2; c++) {
        __syncthreads();
        // A chunk: 128 rows x 64 halves (8 uint4/row)
#pragma unroll
        for (int t = 0; t < 4; t++) {
            int i = tid + t * 256;
            int row = i >> 3, q = i & 7;
            uint4 v = *(const uint4*)&g_y16[(size_t)(nb + row) * HDIM + c * 64 + q * 8];
            *(uint4*)&As[row * AS_STRIDE + q * 8] = v;
        }
        // B chunk (fp16): rows c*64..+63, 128 halves/row = 16 uint4/row
#pragma unroll
        for (int t = 0; t < 4; t++) {
            int i = tid + t * 256;
            int row = i >> 4, q = i & 15;
            uint4 v = *(const uint4*)&Wh[(size_t)(c * 64 + row) * HDIM + q * 8];
            *(uint4*)&Bs[row * BS_STRIDE + q * 8] = v;
        }
        __syncthreads();

#pragma unroll
        for (int kk = 0; kk < 4; kk++) {
            int k16 = kk * 16;
            uint32_t af[2][4];
#pragma unroll
            for (int mt = 0; mt < 2; mt++) {
                uint32_t a = smem_u32(
                    &As[(m0 + mt * 16 + (lane & 15)) * AS_STRIDE + k16 + (lane >> 4) * 8]);
                ldsm_x4(af[mt][0], af[mt][1], af[mt][2], af[mt][3], a);
            }
            uint32_t bf[8][2];
#pragma unroll
            for (int nt2 = 0; nt2 < 4; nt2++) {
                uint32_t a = smem_u32(
                    &Bs[(k16 + (lane & 15)) * BS_STRIDE + n0 + nt2 * 16 + (lane >> 4) * 8]);
                uint32_t r0, r1, r2, r3;
                ldsm_x4_t(r0, r1, r2, r3, a);
                bf[nt2 * 2 + 0][0] = r0; bf[nt2 * 2 + 0][1] = r1;
                bf[nt2 * 2 + 1][0] = r2; bf[nt2 * 2 + 1][1] = r3;
            }
#pragma unroll
            for (int mt = 0; mt < 2; mt++)
#pragma unroll
                for (int nt = 0; nt < 8; nt++)
                    mma16816(acc[mt][nt], af[mt], bf[nt][0], bf[nt][1]);
        }
    }

    // Staged epilogue: scale rows by dinv, fp16 into smem, coalesced stores.
    __syncthreads();
    int tg = lane >> 2, tp = lane & 3;
#pragma unroll
    for (int mt = 0; mt < 2; mt++) {
        int r0 = m0 + mt * 16 + tg;
        float dA = g_dinv[nb + r0];         // rows < MAXN by construction
        float dB = g_dinv[nb + r0 + 8];
#pragma unroll
        for (int nt = 0; nt < 8; nt++) {
            int col = n0 + nt * 8 + 2 * tp;
            __half2 hA = __floats2half2_rn(acc[mt][nt].x * dA, acc[mt][nt].y * dA);
            __half2 hB = __floats2half2_rn(acc[mt][nt].z * dB, acc[mt][nt].w * dB);
            *(__half2*)&Cs[r0 * CS_STRIDE + col] = hA;
            *(__half2*)&Cs[(r0 + 8) * CS_STRIDE + col] = hB;
        }
    }
    __syncthreads();
#pragma unroll
    for (int t = 0; t < 8; t++) {
        int i = tid + t * 256;
        int row = i >> 4, q = i & 15;
        int node = nb + row;
        if (node < N) {
            uint4 v = *(const uint4*)&Cs[row * CS_STRIDE + q * 8];
            *(uint4*)&g_h16[(size_t)node * HDIM + q * 8] = v;
        }
    }
}

// --- CSR aggregation: y[d] = relu(b + dinv[d]*(h'[d] + sum h'[src])) --------
__global__ void __launch_bounds__(256)
agg16_kernel(const float* __restrict__ b, int N, int mode,
             const idx_t* __restrict__ batch, int G) {
    int n = blockIdx.x * 8 + (threadIdx.x >> 5);
    if (n >= N) return;
    int lane = threadIdx.x & 31;

    // Edge sum (pure adds; normalization factored out)
    float4 acc = make_float4(0.f, 0.f, 0.f, 0.f);
    int e = g_off[n];
    int end = e + g_cnt[n];
    for (; e + 3 < end; e += 4) {
        int s0 = g_csr_src[e],     s1 = g_csr_src[e + 1];
        int s2 = g_csr_src[e + 2], s3 = g_csr_src[e + 3];
        uint2 u0 = *(const uint2*)&g_h16[(size_t)s0 * HDIM + lane * 4];
        uint2 u1 = *(const uint2*)&g_h16[(size_t)s1 * HDIM + lane * 4];
        uint2 u2 = *(const uint2*)&g_h16[(size_t)s2 * HDIM + lane * 4];
        uint2 u3 = *(const uint2*)&g_h16[(size_t)s3 * HDIM + lane * 4];
        float2 p0 = __half22float2(*(__half2*)&u0.x);
        float2 q0 = __half22float2(*(__half2*)&u0.y);
        float2 p1 = __half22float2(*(__half2*)&u1.x);
        float2 q1 = __half22float2(*(__half2*)&u1.y);
        float2 p2 = __half22float2(*(__half2*)&u2.x);
        float2 q2 = __half22float2(*(__half2*)&u2.y);
        float2 p3 = __half22float2(*(__half2*)&u3.x);
        float2 q3 = __half22float2(*(__half2*)&u3.y);
        acc.x += (p0.x + p1.x) + (p2.x + p3.x);
        acc.y += (p0.y + p1.y) + (p2.y + p3.y);
        acc.z += (q0.x + q1.x) + (q2.x + q3.x);
        acc.w += (q0.y + q1.y) + (q2.y + q3.y);
    }
    for (; e < end; e++) {
        int s0 = g_csr_src[e];
        uint2 u0 = *(const uint2*)&g_h16[(size_t)s0 * HDIM + lane * 4];
        float2 p0 = __half22float2(*(__half2*)&u0.x);
        float2 q0 = __half22float2(*(__half2*)&u0.y);
        acc.x += p0.x; acc.y += p0.y;
        acc.z += q0.x; acc.w += q0.y;
    }

    // Self term + bias + normalization + relu
    float di = g_dinv[n];
    float4 b4 = *(const float4*)&b[lane * 4];
    uint2 hs = *(const uint2*)&g_h16[(size_t)n * HDIM + lane * 4];
    float2 f0 = __half22float2(*(__half2*)&hs.x);
    float2 f1 = __half22float2(*(__half2*)&hs.y);
    acc.x = fmaxf(b4.x + di * (acc.x + f0.x), 0.f);
    acc.y = fmaxf(b4.y + di * (acc.y + f0.y), 0.f);
    acc.z = fmaxf(b4.z + di * (acc.z + f1.x), 0.f);
    acc.w = fmaxf(b4.w + di * (acc.w + f1.y), 0.f);

    if (mode == 0) {
        __half2 h01 = __floats2half2_rn(acc.x, acc.y);
        __half2 h23 = __floats2half2_rn(acc.z, acc.w);
        *(uint2*)&g_y16[(size_t)n * HDIM + lane * 4] =
            make_uint2(*(uint32_t*)&h01, *(uint32_t*)&h23);
    } else {
        int bg = (int)__ldg(&batch[n]);
        if ((unsigned)bg < (unsigned)G) {
            float* p = &g_gsum[bg * HDIM + lane * 4];
            asm volatile("red.global.add.v4.f32 [%0], {%1,%2,%3,%4};"
                         :: "l"(p), "f"(acc.x), "f"(acc.y), "f"(acc.z), "f"(acc.w)
                         : "memory");
            if (lane == 0) atomicAdd(&g_gcnt[bg], 1.0f);
        }
    }
}

// --- Final MLP: one block per graph ------------------------------------------
__global__ void __launch_bounds__(128)
mlp_kernel(const float* __restrict__ Wl1,
           const float* __restrict__ bl1,
           const float* __restrict__ Wl2,
           const float* __restrict__ bl2,
           float* __restrict__ out,
           int H2, int C) {
    __shared__ float xs[HDIM];
    __shared__ float h1[64];
    int g = blockIdx.x;
    int tid = threadIdx.x;

    float inv = 1.0f / fmaxf(g_gcnt[g], 1.0f);
    if (tid < HDIM) xs[tid] = g_gsum[g * HDIM + tid] * inv;
    __syncthreads();

    if (tid < H2) {
        float s = bl1[tid];
        for (int k = 0; k < HDIM; k++)
            s += xs[k] * Wl1[k * H2 + tid];
        h1[tid] = fmaxf(s, 0.f);
    }
    __syncthreads();

    if (tid < C) {
        float s = bl2[tid];
        for (int j = 0; j < H2; j++)
            s += h1[j] * Wl2[j * C + tid];
        out[g * C + tid] = s;
    }
}

// ---------------------------------------------------------------------------
extern "C" void kernel_launch(void* const* d_in, const int* in_sizes, int n_in,
                              void* d_out, int out_size) {
    const float* pos  = (const float*)d_in[0];
    const idx_t* ei   = (const idx_t*)d_in[1];
    const idx_t* batch= (const idx_t*)d_in[2];
    const float* W1   = (const float*)d_in[3];
    const float* b1   = (const float*)d_in[4];
    const float* W2   = (const float*)d_in[5];
    const float* b2   = (const float*)d_in[6];
    const float* W3   = (const float*)d_in[7];
    const float* b3   = (const float*)d_in[8];
    const float* Wl1  = (const float*)d_in[9];
    const float* bl1  = (const float*)d_in[10];
    const float* Wl2  = (const float*)d_in[11];
    const float* bl2  = (const float*)d_in[12];
    float* out = (float*)d_out;

    int H  = in_sizes[4];              // 128
    int D  = in_sizes[3] / H;          // 3
    int N  = in_sizes[0] / D;          // 50000
    int E  = in_sizes[1] / 2;          // 800000
    int H2 = in_sizes[10];             // 64
    int C  = in_sizes[12];             // 10
    int G  = out_size / C;             // 64

    int initN = N > G * H ? N : G * H;
    setup_kernel<<<(initN + 255) / 256, 256>>>(W2, W3, N, G * H, G);
    hist_kernel<<<(E + 255) / 256, 256>>>(ei, E, N);
    scan_kernel<<<(N + SCAN_CHUNK - 1) / SCAN_CHUNK, SCAN_THREADS>>>(pos, N);
    edge_fill<<<(E + 255) / 256, 256>>>(ei, E, N);

    // Layer 1 (fused: pos'-space aggregation + dense + relu)
    layer1_kernel<<<(N + 7) / 8, 256>>>(W1, b1, N);

    // Layer 2
    dense_mma_kernel<<<(N + 127) / 128, 256>>>(2, N);
    agg16_kernel<<<(N + 7) / 8, 256>>>(b2, N, 0, batch, G);

    // Layer 3 (aggregation fused with mean-pool)
    dense_mma_kernel<<<(N + 127) / 128, 256>>>(3, N);
    agg16_kernel<<<(N + 7) / 8, 256>>>(b3, N, 1, batch, G);

    mlp_kernel<<<G, 128>>>(Wl1, bl1, Wl2, bl2, out, H2, C);
}